// round 4
// baseline (speedup 1.0000x reference)
#include <cuda_runtime.h>
#include <stdint.h>
#include <math.h>

// Problem constants
#define H   24
#define Nn  3072
#define D   128
#define BMQ 192          // query-group block size
#define G   16           // groups per head (Nn / BMQ)
#define HG  (H * G)      // 384
#define TOPK 896
#define MAXL 4096        // per-group index list stride (topk + random, generous)

// ---------------- device scratch (static: no runtime allocation) -------------
__device__ float g_S[(size_t)H * Nn * Nn];   // S then P in-place  (~906 MB)
__device__ float g_cs[HG * Nn];              // per-group column sums
__device__ int   g_idx[HG * MAXL];           // compacted selected column indices
__device__ int   g_cnt[HG];                  // selected count per group

// ---------------- threefry2x32 (JAX / Random123 compatible, 20 rounds) -------
#define TF_ROUND(x0, x1, r) { x0 += x1; x1 = (x1 << r) | (x1 >> (32 - r)); x1 ^= x0; }

__device__ __forceinline__ uint2 tf2x32(unsigned k0, unsigned k1,
                                        unsigned c0, unsigned c1) {
    unsigned ks2 = k0 ^ k1 ^ 0x1BD11BDAu;
    unsigned x0 = c0 + k0, x1 = c1 + k1;
    TF_ROUND(x0, x1, 13) TF_ROUND(x0, x1, 15) TF_ROUND(x0, x1, 26) TF_ROUND(x0, x1, 6)
    x0 += k1;  x1 += ks2 + 1u;
    TF_ROUND(x0, x1, 17) TF_ROUND(x0, x1, 29) TF_ROUND(x0, x1, 16) TF_ROUND(x0, x1, 24)
    x0 += ks2; x1 += k0 + 2u;
    TF_ROUND(x0, x1, 13) TF_ROUND(x0, x1, 15) TF_ROUND(x0, x1, 26) TF_ROUND(x0, x1, 6)
    x0 += k0;  x1 += k1 + 3u;
    TF_ROUND(x0, x1, 17) TF_ROUND(x0, x1, 29) TF_ROUND(x0, x1, 16) TF_ROUND(x0, x1, 24)
    x0 += k1;  x1 += ks2 + 4u;
    TF_ROUND(x0, x1, 13) TF_ROUND(x0, x1, 15) TF_ROUND(x0, x1, 26) TF_ROUND(x0, x1, 6)
    x0 += ks2; x1 += k0 + 5u;
    return make_uint2(x0, x1);
}

// partitionable random_bits (32-bit): element f drawn as xor of the two output
// words of threefry2x32(key, (hi32(f), lo32(f))); here f < 2^32 so hi=0.
__device__ __forceinline__ unsigned tf_bits32(unsigned k0, unsigned k1, unsigned f) {
    uint2 o = tf2x32(k0, k1, 0u, f);
    return o.x ^ o.y;
}

// =============================================================================
// K1: S[h, m, n] = scale * q[h, m, :] . k[h, n, :]
//     128x128 block tile, 256 threads, 8x8 micro-tile, BK=16
// =============================================================================
__global__ __launch_bounds__(256) void qk_kernel(const float* __restrict__ q,
                                                 const float* __restrict__ k) {
    const int h  = blockIdx.z;
    const int bm = blockIdx.x * 128;
    const int bn = blockIdx.y * 128;
    const float* Q = q + (size_t)h * Nn * D;
    const float* K = k + (size_t)h * Nn * D;
    float*       S = g_S + (size_t)h * Nn * Nn;

    __shared__ float As[16][128];
    __shared__ float Bs[16][128];

    const int t  = threadIdx.x;
    const int tx = t & 15, ty = t >> 4;
    const int m0 = ty * 8, n0 = tx * 8;

    float acc[8][8];
#pragma unroll
    for (int i = 0; i < 8; i++)
#pragma unroll
        for (int j = 0; j < 8; j++) acc[i][j] = 0.f;

    for (int k0 = 0; k0 < D; k0 += 16) {
#pragma unroll
        for (int it = 0; it < 2; it++) {
            int lin = it * 256 + t;         // 0..511 float4 slots
            int row = lin & 127;
            int c4  = lin >> 7;             // 0..3
            float4 a = *reinterpret_cast<const float4*>(&Q[(size_t)(bm + row) * D + k0 + c4 * 4]);
            As[c4 * 4 + 0][row] = a.x; As[c4 * 4 + 1][row] = a.y;
            As[c4 * 4 + 2][row] = a.z; As[c4 * 4 + 3][row] = a.w;
            float4 b = *reinterpret_cast<const float4*>(&K[(size_t)(bn + row) * D + k0 + c4 * 4]);
            Bs[c4 * 4 + 0][row] = b.x; Bs[c4 * 4 + 1][row] = b.y;
            Bs[c4 * 4 + 2][row] = b.z; Bs[c4 * 4 + 3][row] = b.w;
        }
        __syncthreads();
#pragma unroll
        for (int kk = 0; kk < 16; kk++) {
            float a[8], b[8];
#pragma unroll
            for (int i = 0; i < 8; i++) a[i] = As[kk][m0 + i];
#pragma unroll
            for (int j = 0; j < 8; j++) b[j] = Bs[kk][n0 + j];
#pragma unroll
            for (int i = 0; i < 8; i++)
#pragma unroll
                for (int j = 0; j < 8; j++) acc[i][j] += a[i] * b[j];
        }
        __syncthreads();
    }

    const float scale = 0.08838834764831845f;  // 1/sqrt(128)
#pragma unroll
    for (int i = 0; i < 8; i++) {
#pragma unroll
        for (int j = 0; j < 8; j += 4) {
            float4 o;
            o.x = acc[i][j + 0] * scale; o.y = acc[i][j + 1] * scale;
            o.z = acc[i][j + 2] * scale; o.w = acc[i][j + 3] * scale;
            *reinterpret_cast<float4*>(&S[(size_t)(bm + m0 + i) * Nn + bn + n0 + j]) = o;
        }
    }
}

// =============================================================================
// K2: row softmax in place (S -> P)
// =============================================================================
__global__ __launch_bounds__(256) void softmax_kernel() {
    const int h = blockIdx.y, r = blockIdx.x;
    float* row = g_S + (size_t)h * Nn * Nn + (size_t)r * Nn;

    __shared__ float sm[Nn];
    __shared__ float red[256];
    const int t = threadIdx.x;

    float mx = -INFINITY;
    for (int j = t; j < Nn; j += 256) { float v = row[j]; sm[j] = v; mx = fmaxf(mx, v); }
    red[t] = mx; __syncthreads();
    for (int s = 128; s > 0; s >>= 1) { if (t < s) red[t] = fmaxf(red[t], red[t + s]); __syncthreads(); }
    const float rowmax = red[0];
    __syncthreads();

    float sum = 0.f;
    for (int j = t; j < Nn; j += 256) { float e = expf(sm[j] - rowmax); sm[j] = e; sum += e; }
    red[t] = sum; __syncthreads();
    for (int s = 128; s > 0; s >>= 1) { if (t < s) red[t] += red[t + s]; __syncthreads(); }
    const float inv = 1.f / red[0];
    __syncthreads();

    for (int j = t; j < Nn; j += 256) row[j] = sm[j] * inv;
}

// =============================================================================
// K3: column sums per query group: cs[h,g,j] = sum_{m<192} P[h, g*192+m, j]
// =============================================================================
__global__ __launch_bounds__(256) void cs_kernel() {
    const int h = blockIdx.z, g = blockIdx.y;
    const int j = blockIdx.x * 256 + threadIdx.x;
    const float* P = g_S + (size_t)h * Nn * Nn + (size_t)g * BMQ * Nn;
    float s = 0.f;
#pragma unroll 4
    for (int m = 0; m < BMQ; m++) s += P[(size_t)m * Nn + j];
    g_cs[(h * G + g) * Nn + j] = s;
}

// =============================================================================
// K4: O = P @ V  (per head, M=3072, N=128, K=3072), writes d_out first half
// =============================================================================
__global__ __launch_bounds__(256) void pv_kernel(const float* __restrict__ v,
                                                 float* __restrict__ out) {
    const int h  = blockIdx.z;
    const int bm = blockIdx.x * 128;
    const float* P = g_S + (size_t)h * Nn * Nn;
    const float* V = v + (size_t)h * Nn * D;

    __shared__ float As[16][128];
    __shared__ float Bs[16][128];

    const int t  = threadIdx.x;
    const int tx = t & 15, ty = t >> 4;
    const int m0 = ty * 8, n0 = tx * 8;

    float acc[8][8];
#pragma unroll
    for (int i = 0; i < 8; i++)
#pragma unroll
        for (int j = 0; j < 8; j++) acc[i][j] = 0.f;

    for (int k0 = 0; k0 < Nn; k0 += 16) {
#pragma unroll
        for (int it = 0; it < 2; it++) {
            int lin = it * 256 + t;
            int row = lin & 127;
            int c4  = lin >> 7;
            float4 a = *reinterpret_cast<const float4*>(&P[(size_t)(bm + row) * Nn + k0 + c4 * 4]);
            As[c4 * 4 + 0][row] = a.x; As[c4 * 4 + 1][row] = a.y;
            As[c4 * 4 + 2][row] = a.z; As[c4 * 4 + 3][row] = a.w;
            int kk = lin >> 5;          // 0..15
            int d4 = lin & 31;          // 0..31
            float4 b = *reinterpret_cast<const float4*>(&V[(size_t)(k0 + kk) * D + d4 * 4]);
            *reinterpret_cast<float4*>(&Bs[kk][d4 * 4]) = b;
        }
        __syncthreads();
#pragma unroll
        for (int kk = 0; kk < 16; kk++) {
            float a[8], b[8];
#pragma unroll
            for (int i = 0; i < 8; i++) a[i] = As[kk][m0 + i];
#pragma unroll
            for (int j = 0; j < 8; j++) b[j] = Bs[kk][n0 + j];
#pragma unroll
            for (int i = 0; i < 8; i++)
#pragma unroll
                for (int j = 0; j < 8; j++) acc[i][j] += a[i] * b[j];
        }
        __syncthreads();
    }

#pragma unroll
    for (int i = 0; i < 8; i++) {
#pragma unroll
        for (int j = 0; j < 8; j += 4) {
            float4 o;
            o.x = acc[i][j + 0]; o.y = acc[i][j + 1]; o.z = acc[i][j + 2]; o.w = acc[i][j + 3];
            *reinterpret_cast<float4*>(&out[(size_t)h * Nn * D + (size_t)(bm + m0 + i) * D + n0 + j]) = o;
        }
    }
}

// =============================================================================
// K5: per (h,g): exact top-896 radix select + threefry random mask + compaction
// =============================================================================
__global__ __launch_bounds__(256) void select_kernel() {
    const int hg = blockIdx.x;                 // hg = h*G + g
    const float* cs = g_cs + hg * Nn;
    const int t = threadIdx.x;

    __shared__ unsigned keys[Nn];
    __shared__ unsigned hist[256];
    __shared__ unsigned char mk[Nn];
    __shared__ int scan[256];
    __shared__ unsigned sh_prefix, sh_need;
    __shared__ int base_;

    // monotonic float -> uint mapping
    for (int j = t; j < Nn; j += 256) {
        unsigned u = __float_as_uint(cs[j]);
        keys[j] = (u & 0x80000000u) ? ~u : (u | 0x80000000u);
        mk[j] = 0;
    }
    __syncthreads();

    // 4-pass radix select for the TOPK-th largest key
    unsigned prefix = 0, kneed = TOPK;
    for (int shift = 24; shift >= 0; shift -= 8) {
        hist[t] = 0;
        __syncthreads();
        const unsigned himask = (shift == 24) ? 0u : (0xFFFFFFFFu << (shift + 8));
        for (int j = t; j < Nn; j += 256) {
            unsigned u = keys[j];
            if (((u ^ prefix) & himask) == 0)
                atomicAdd(&hist[(u >> shift) & 255u], 1u);
        }
        __syncthreads();
        if (t == 0) {
            unsigned cum = 0; int b = 255;
            for (; b > 0; b--) {
                if (cum + hist[b] >= kneed) break;
                cum += hist[b];
            }
            sh_prefix = prefix | ((unsigned)b << shift);
            sh_need   = kneed - cum;
        }
        __syncthreads();
        prefix = sh_prefix; kneed = sh_need;
        __syncthreads();
    }
    const unsigned T = prefix;   // exact key of TOPK-th largest; kneed ties to take

    for (int j = t; j < Nn; j += 256)
        if (keys[j] > T) mk[j] = 1;
    __syncthreads();
    if (t == 0) {                // ties: lowest indices first (lax.top_k stability)
        int need = (int)kneed;
        for (int j = 0; j < Nn && need > 0; j++)
            if (keys[j] == T) { mk[j] = 1; need--; }
    }
    __syncthreads();

    // ---- threefry random mask, partitionable semantics ----
    // split(key(1)) fold-like: subkey_i = full output of tf2x32((0,1),(0,i))
    uint2 hk = tf2x32(0u, 1u, 0u, 0u);   // higher_key
    uint2 lk = tf2x32(0u, 1u, 0u, 1u);   // lower_key
    // randint: offset = ((hi%100)*96 + lo%100) % 100 ; mask where offset==0
    for (int j = t; j < Nn; j += 256) {
        unsigned f = (unsigned)(hg * Nn + j);          // flat index (< 2^32)
        unsigned hi = tf_bits32(hk.x, hk.y, f);
        unsigned lo = tf_bits32(lk.x, lk.y, f);
        unsigned off = ((hi % 100u) * 96u + (lo % 100u)) % 100u;
        if (off == 0u) mk[j] = 1;
    }
    __syncthreads();

    // stable compaction to g_idx (ascending column index)
    if (t == 0) base_ = 0;
    __syncthreads();
    for (int j0 = 0; j0 < Nn; j0 += 256) {
        int flag = mk[j0 + t];
        scan[t] = flag;
        __syncthreads();
        for (int s = 1; s < 256; s <<= 1) {
            int v = (t >= s) ? scan[t - s] : 0;
            __syncthreads();
            scan[t] += v;
            __syncthreads();
        }
        int incl = scan[t];
        if (flag) g_idx[hg * MAXL + base_ + incl - 1] = j0 + t;
        __syncthreads();
        if (t == 255) base_ += incl;
        __syncthreads();
    }
    if (t == 0) g_cnt[hg] = base_;
}

// =============================================================================
// K6: sparse attention + final subtraction:
//     out2[r,:] = O[r,:] - (sum_{c in list} P[r,c] * V[c,:]) / (sum_c P[r,c])
// =============================================================================
__global__ __launch_bounds__(256) void sparse_kernel(const float* __restrict__ v,
                                                     float* __restrict__ out) {
    const int h = blockIdx.z, g = blockIdx.y, rc = blockIdx.x;
    const int hg = h * G + g;
    const int row0 = g * BMQ + rc * 64;
    const float* P = g_S + (size_t)h * Nn * Nn;
    const float* V = v + (size_t)h * Nn * D;
    const int L = g_cnt[hg];
    const int* lst = g_idx + hg * MAXL;

    __shared__ float Ps[64][17];
    __shared__ float Vs[16][128];
    __shared__ int   sIdx[16];
    __shared__ float sden[64];

    const int t = threadIdx.x;
    const int tx = t & 15, ty = t >> 4;
    const int m0 = ty * 4, n0 = tx * 8;

    float acc[4][8];
#pragma unroll
    for (int i = 0; i < 4; i++)
#pragma unroll
        for (int j = 0; j < 8; j++) acc[i][j] = 0.f;
    float den[4] = {0.f, 0.f, 0.f, 0.f};

    for (int l0 = 0; l0 < L; l0 += 16) {
        const int nl = min(16, L - l0);
        if (t < 16) sIdx[t] = (t < nl) ? lst[l0 + t] : -1;
        __syncthreads();
#pragma unroll
        for (int it = 0; it < 4; it++) {        // Ps gather: 64 rows x 16 cols
            int e = it * 256 + t;
            int r = e & 63, c = e >> 6;
            int col = sIdx[c];
            Ps[r][c] = (col >= 0) ? P[(size_t)(row0 + r) * Nn + col] : 0.f;
        }
#pragma unroll
        for (int it = 0; it < 2; it++) {        // Vs: 16 rows x 128 d
            int e = it * 256 + t;
            int kk = e >> 5, d4 = e & 31;
            int col = sIdx[kk];
            float4 val = (col >= 0)
                ? *reinterpret_cast<const float4*>(&V[(size_t)col * D + d4 * 4])
                : make_float4(0.f, 0.f, 0.f, 0.f);
            *reinterpret_cast<float4*>(&Vs[kk][d4 * 4]) = val;
        }
        __syncthreads();
#pragma unroll
        for (int kk = 0; kk < 16; kk++) {
            float a[4], b[8];
#pragma unroll
            for (int i = 0; i < 4; i++) a[i] = Ps[m0 + i][kk];
#pragma unroll
            for (int j = 0; j < 8; j++) b[j] = Vs[kk][n0 + j];
#pragma unroll
            for (int i = 0; i < 4; i++)
#pragma unroll
                for (int j = 0; j < 8; j++) acc[i][j] += a[i] * b[j];
            if (tx == 0) {
#pragma unroll
                for (int i = 0; i < 4; i++) den[i] += a[i];
            }
        }
        __syncthreads();
    }

    if (tx == 0) {
#pragma unroll
        for (int i = 0; i < 4; i++) sden[m0 + i] = den[i];
    }
    __syncthreads();

    const size_t obase = (size_t)h * Nn * D;
    float* out2 = out + (size_t)H * Nn * D;
#pragma unroll
    for (int i = 0; i < 4; i++) {
        const int r = row0 + m0 + i;
        const float dinv = 1.f / sden[m0 + i];
#pragma unroll
        for (int j = 0; j < 8; j++) {
            const int dc = n0 + j;
            float o_ = out[obase + (size_t)r * D + dc];
            out2[obase + (size_t)r * D + dc] = o_ - acc[i][j] * dinv;
        }
    }
}

// =============================================================================
extern "C" void kernel_launch(void* const* d_in, const int* in_sizes, int n_in,
                              void* d_out, int out_size) {
    const float* q = (const float*)d_in[0];
    const float* k = (const float*)d_in[1];
    const float* v = (const float*)d_in[2];
    float* out = (float*)d_out;

    qk_kernel<<<dim3(Nn / 128, Nn / 128, H), 256>>>(q, k);
    softmax_kernel<<<dim3(Nn, H), 256>>>();
    cs_kernel<<<dim3(Nn / 256, G, H), 256>>>();
    pv_kernel<<<dim3(Nn / 128, 1, H), 256>>>(v, out);
    select_kernel<<<HG, 256>>>();
    sparse_kernel<<<dim3(3, G, H), 256>>>(v, out);
}

// round 9
// speedup vs baseline: 1.0166x; 1.0166x over previous
#include <cuda_runtime.h>
#include <cuda_bf16.h>
#include <stdint.h>
#include <math.h>

// Problem constants
#define H   24
#define Nn  3072
#define D   128
#define BMQ 192
#define G   16
#define HG  (H * G)
#define TOPK 896
#define MAXL 4096

// ---------------- device scratch (static; no runtime allocation) -------------
__device__ float g_S[(size_t)H * Nn * Nn];       // S then P (fp32, in place)
__device__ float g_cs[HG * Nn];
__device__ int   g_idx[HG * MAXL];
__device__ int   g_cnt[HG];
// 3-way split planes for Q and K (a + b + c, each bf16)
__device__ __nv_bfloat16 g_qa[(size_t)H * Nn * D];
__device__ __nv_bfloat16 g_qb[(size_t)H * Nn * D];
__device__ __nv_bfloat16 g_qc[(size_t)H * Nn * D];
__device__ __nv_bfloat16 g_ka[(size_t)H * Nn * D];
__device__ __nv_bfloat16 g_kb[(size_t)H * Nn * D];
__device__ __nv_bfloat16 g_kc[(size_t)H * Nn * D];
// 2-way split V^T planes [h][d][k]
__device__ __nv_bfloat16 g_vth[(size_t)H * D * Nn];
__device__ __nv_bfloat16 g_vtl[(size_t)H * D * Nn];

// ---------------- helpers ----------------------------------------------------
__device__ __forceinline__ uint32_t smem_to_u32(const void* p) {
    uint32_t a;
    asm("{ .reg .u64 t; cvta.to.shared.u64 t, %1; cvt.u32.u64 %0, t; }" : "=r"(a) : "l"(p));
    return a;
}

__device__ __forceinline__ void ldsm_x4(uint32_t& r0, uint32_t& r1, uint32_t& r2,
                                        uint32_t& r3, uint32_t addr) {
    asm volatile("ldmatrix.sync.aligned.m8n8.x4.shared.b16 {%0,%1,%2,%3}, [%4];"
                 : "=r"(r0), "=r"(r1), "=r"(r2), "=r"(r3) : "r"(addr));
}

__device__ __forceinline__ void mma_bf16(float* c, const uint32_t* a, const uint32_t* b) {
    asm volatile(
        "mma.sync.aligned.m16n8k16.row.col.f32.bf16.bf16.f32 "
        "{%0,%1,%2,%3}, {%4,%5,%6,%7}, {%8,%9}, {%0,%1,%2,%3};"
        : "+f"(c[0]), "+f"(c[1]), "+f"(c[2]), "+f"(c[3])
        : "r"(a[0]), "r"(a[1]), "r"(a[2]), "r"(a[3]), "r"(b[0]), "r"(b[1]));
}

// smem tile: 128 rows x 256B (128 bf16), 16B chunks xor-swizzled by row%8
__device__ __forceinline__ uint32_t sw_off(int row, int c16) {
    return (uint32_t)(row * 256 + ((c16 ^ (row & 7)) << 4));
}

#define PLANE 32768

// ---------------- threefry2x32 ----------------------------------------------
#define TF_ROUND(x0, x1, r) { x0 += x1; x1 = (x1 << r) | (x1 >> (32 - r)); x1 ^= x0; }
__device__ __forceinline__ uint2 tf2x32(unsigned k0, unsigned k1, unsigned c0, unsigned c1) {
    unsigned ks2 = k0 ^ k1 ^ 0x1BD11BDAu;
    unsigned x0 = c0 + k0, x1 = c1 + k1;
    TF_ROUND(x0, x1, 13) TF_ROUND(x0, x1, 15) TF_ROUND(x0, x1, 26) TF_ROUND(x0, x1, 6)
    x0 += k1;  x1 += ks2 + 1u;
    TF_ROUND(x0, x1, 17) TF_ROUND(x0, x1, 29) TF_ROUND(x0, x1, 16) TF_ROUND(x0, x1, 24)
    x0 += ks2; x1 += k0 + 2u;
    TF_ROUND(x0, x1, 13) TF_ROUND(x0, x1, 15) TF_ROUND(x0, x1, 26) TF_ROUND(x0, x1, 6)
    x0 += k0;  x1 += k1 + 3u;
    TF_ROUND(x0, x1, 17) TF_ROUND(x0, x1, 29) TF_ROUND(x0, x1, 16) TF_ROUND(x0, x1, 24)
    x0 += k1;  x1 += ks2 + 4u;
    TF_ROUND(x0, x1, 13) TF_ROUND(x0, x1, 15) TF_ROUND(x0, x1, 26) TF_ROUND(x0, x1, 6)
    x0 += ks2; x1 += k0 + 5u;
    return make_uint2(x0, x1);
}
__device__ __forceinline__ unsigned tf_bits32(unsigned k0, unsigned k1, unsigned f) {
    uint2 o = tf2x32(k0, k1, 0u, f);
    return o.x ^ o.y;
}

// =============================================================================
// K0a: split q,k into 3 bf16 planes (a + b + c)
// =============================================================================
__global__ __launch_bounds__(256) void split_qk_kernel(const float* __restrict__ q,
                                                       const float* __restrict__ k) {
    const int which = blockIdx.y;
    const float* src = which ? k : q;
    __nv_bfloat16* da = which ? g_ka : g_qa;
    __nv_bfloat16* db = which ? g_kb : g_qb;
    __nv_bfloat16* dc = which ? g_kc : g_qc;
    size_t i = (size_t)blockIdx.x * 256 + threadIdx.x;   // float4 index
    float4 x = reinterpret_cast<const float4*>(src)[i];
    float v[4] = {x.x, x.y, x.z, x.w};
    unsigned short as_[4], bs[4], cs_[4];
#pragma unroll
    for (int j = 0; j < 4; j++) {
        __nv_bfloat16 ab = __float2bfloat16_rn(v[j]);
        float r1 = v[j] - __bfloat162float(ab);
        __nv_bfloat16 bb = __float2bfloat16_rn(r1);
        float r2 = r1 - __bfloat162float(bb);
        __nv_bfloat16 cb = __float2bfloat16_rn(r2);
        as_[j] = __bfloat16_as_ushort(ab);
        bs[j]  = __bfloat16_as_ushort(bb);
        cs_[j] = __bfloat16_as_ushort(cb);
    }
    uint2 av, bv, cv;
    av.x = (uint32_t)as_[0] | ((uint32_t)as_[1] << 16);
    av.y = (uint32_t)as_[2] | ((uint32_t)as_[3] << 16);
    bv.x = (uint32_t)bs[0]  | ((uint32_t)bs[1] << 16);
    bv.y = (uint32_t)bs[2]  | ((uint32_t)bs[3] << 16);
    cv.x = (uint32_t)cs_[0] | ((uint32_t)cs_[1] << 16);
    cv.y = (uint32_t)cs_[2] | ((uint32_t)cs_[3] << 16);
    reinterpret_cast<uint2*>(da)[i] = av;
    reinterpret_cast<uint2*>(db)[i] = bv;
    reinterpret_cast<uint2*>(dc)[i] = cv;
}

// =============================================================================
// K0b: transpose + split V -> VT hi/lo planes [h][d][k]
// =============================================================================
__global__ void vtrans_kernel(const float* __restrict__ v) {
    const int h = blockIdx.z, k0 = blockIdx.x * 32, d0 = blockIdx.y * 32;
    __shared__ float tile[32][33];
    const int tx = threadIdx.x, ty = threadIdx.y;
    const float* V = v + (size_t)h * Nn * D;
    for (int r = ty; r < 32; r += 8)
        tile[r][tx] = V[(size_t)(k0 + r) * D + d0 + tx];
    __syncthreads();
    for (int r = ty; r < 32; r += 8) {
        float val = tile[tx][r];
        __nv_bfloat16 hb = __float2bfloat16_rn(val);
        float rem = val - __bfloat162float(hb);
        __nv_bfloat16 lb = __float2bfloat16_rn(rem);
        size_t o = (size_t)h * D * Nn + (size_t)(d0 + r) * Nn + k0 + tx;
        g_vth[o] = hb;
        g_vtl[o] = lb;
    }
}

// =============================================================================
// K1: S = scale * Q K^T via mma.sync bf16, 3-way split (6 products)
//     CTA: 128x128 tile, 128 threads (4 warps, each 64x64), K=128 single fill
//     smem planes: 0:Qa 1:Qb 2:Qc 3:Ka 4:Kb 5:Kc
// =============================================================================
__global__ __launch_bounds__(128) void qk_mma_kernel() {
    extern __shared__ char smem[];
    const uint32_t sb = smem_to_u32(smem);
    const int t = threadIdx.x, lane = t & 31, wid = t >> 5;
    const int h = blockIdx.z, bm = blockIdx.x * 128, bn = blockIdx.y * 128;

    {   // fill 6 planes
        const size_t qg = (size_t)h * Nn * D + (size_t)bm * D;
        const size_t kg = (size_t)h * Nn * D + (size_t)bn * D;
        const __nv_bfloat16* s0 = g_qa + qg;
        const __nv_bfloat16* s1 = g_qb + qg;
        const __nv_bfloat16* s2 = g_qc + qg;
        const __nv_bfloat16* s3 = g_ka + kg;
        const __nv_bfloat16* s4 = g_kb + kg;
        const __nv_bfloat16* s5 = g_kc + kg;
        for (int i = t; i < 2048; i += 128) {
            int row = i >> 4, c16 = i & 15;
            uint32_t o = sw_off(row, c16);
            size_t g = (size_t)row * D + c16 * 8;
            *reinterpret_cast<uint4*>(smem + o)             = *reinterpret_cast<const uint4*>(s0 + g);
            *reinterpret_cast<uint4*>(smem + PLANE + o)     = *reinterpret_cast<const uint4*>(s1 + g);
            *reinterpret_cast<uint4*>(smem + 2 * PLANE + o) = *reinterpret_cast<const uint4*>(s2 + g);
            *reinterpret_cast<uint4*>(smem + 3 * PLANE + o) = *reinterpret_cast<const uint4*>(s3 + g);
            *reinterpret_cast<uint4*>(smem + 4 * PLANE + o) = *reinterpret_cast<const uint4*>(s4 + g);
            *reinterpret_cast<uint4*>(smem + 5 * PLANE + o) = *reinterpret_cast<const uint4*>(s5 + g);
        }
    }
    __syncthreads();

    const int m0 = (wid >> 1) * 64, n0 = (wid & 1) * 64;
    float acc[4][8][4];
#pragma unroll
    for (int i = 0; i < 4; i++)
#pragma unroll
        for (int j = 0; j < 8; j++)
#pragma unroll
            for (int c = 0; c < 4; c++) acc[i][j][c] = 0.f;

#pragma unroll
    for (int kk = 0; kk < 8; kk++) {
        const int arow = (lane & 15), ach = kk * 2 + (lane >> 4);
        uint32_t A[4][4], B[8][2];
        // B planes: bi=0 -> Ka needs {Qa,Qb,Qc}; bi=1 -> Kb needs {Qa,Qb}; bi=2 -> Kc needs {Qa}
#pragma unroll
        for (int bi = 0; bi < 3; bi++) {
#pragma unroll
            for (int nj = 0; nj < 4; nj++) {
                int row = n0 + nj * 16 + arow;
                uint32_t r0, r1, r2, r3;
                ldsm_x4(r0, r1, r2, r3, sb + (3 + bi) * PLANE + sw_off(row, ach));
                B[nj * 2][0] = r0; B[nj * 2][1] = r2;
                B[nj * 2 + 1][0] = r1; B[nj * 2 + 1][1] = r3;
            }
            const int nA = (bi == 0) ? 3 : (bi == 1) ? 2 : 1;
#pragma unroll
            for (int ai = 0; ai < 3; ai++) {
                if (ai >= nA) continue;
#pragma unroll
                for (int mi = 0; mi < 4; mi++) {
                    int row = m0 + mi * 16 + arow;
                    ldsm_x4(A[mi][0], A[mi][1], A[mi][2], A[mi][3],
                            sb + ai * PLANE + sw_off(row, ach));
                }
#pragma unroll
                for (int mi = 0; mi < 4; mi++)
#pragma unroll
                    for (int ni = 0; ni < 8; ni++)
                        mma_bf16(acc[mi][ni], A[mi], B[ni]);
            }
        }
    }

    const float scale = 0.08838834764831845f;
    float* S = g_S + (size_t)h * Nn * Nn;
#pragma unroll
    for (int mi = 0; mi < 4; mi++) {
#pragma unroll
        for (int nj = 0; nj < 8; nj++) {
            int r = bm + m0 + mi * 16 + (lane >> 2);
            int c = bn + n0 + nj * 8 + (lane & 3) * 2;
            float2 v01 = make_float2(acc[mi][nj][0] * scale, acc[mi][nj][1] * scale);
            float2 v23 = make_float2(acc[mi][nj][2] * scale, acc[mi][nj][3] * scale);
            *reinterpret_cast<float2*>(&S[(size_t)r * Nn + c]) = v01;
            *reinterpret_cast<float2*>(&S[(size_t)(r + 8) * Nn + c]) = v23;
        }
    }
}

// =============================================================================
// K2: row softmax in place (fp32, validated)
// =============================================================================
__global__ __launch_bounds__(256) void softmax_kernel() {
    const int h = blockIdx.y, r = blockIdx.x;
    float* row = g_S + (size_t)h * Nn * Nn + (size_t)r * Nn;

    __shared__ float sm[Nn];
    __shared__ float red[256];
    const int t = threadIdx.x;

    float mx = -INFINITY;
    for (int j = t; j < Nn; j += 256) { float v = row[j]; sm[j] = v; mx = fmaxf(mx, v); }
    red[t] = mx; __syncthreads();
    for (int s = 128; s > 0; s >>= 1) { if (t < s) red[t] = fmaxf(red[t], red[t + s]); __syncthreads(); }
    const float rowmax = red[0];
    __syncthreads();

    float sum = 0.f;
    for (int j = t; j < Nn; j += 256) { float e = expf(sm[j] - rowmax); sm[j] = e; sum += e; }
    red[t] = sum; __syncthreads();
    for (int s = 128; s > 0; s >>= 1) { if (t < s) red[t] += red[t + s]; __syncthreads(); }
    const float inv = 1.f / red[0];
    __syncthreads();

    for (int j = t; j < Nn; j += 256) row[j] = sm[j] * inv;
}

// =============================================================================
// K3: column sums per query group (fp32, validated)
// =============================================================================
__global__ __launch_bounds__(256) void cs_kernel() {
    const int h = blockIdx.z, g = blockIdx.y;
    const int j = blockIdx.x * 256 + threadIdx.x;
    const float* P = g_S + (size_t)h * Nn * Nn + (size_t)g * BMQ * Nn;
    float s = 0.f;
#pragma unroll 4
    for (int m = 0; m < BMQ; m++) s += P[(size_t)m * Nn + j];
    g_cs[(h * G + g) * Nn + j] = s;
}

// =============================================================================
// K4: O = P @ V via mma.sync bf16 (3-product 2-way split)
// =============================================================================
__global__ __launch_bounds__(128) void pv_mma_kernel(float* __restrict__ out) {
    extern __shared__ char smem[];
    const uint32_t sb = smem_to_u32(smem);
    const int t = threadIdx.x, lane = t & 31, wid = t >> 5;
    const int h = blockIdx.z, bm = blockIdx.x * 128;

    const float* Pp = g_S + (size_t)h * Nn * Nn + (size_t)bm * Nn;
    const __nv_bfloat16* vh = g_vth + (size_t)h * D * Nn;
    const __nv_bfloat16* vl = g_vtl + (size_t)h * D * Nn;

    const int m0 = (wid >> 1) * 64, n0 = (wid & 1) * 64;
    float acc[4][8][4];
#pragma unroll
    for (int i = 0; i < 4; i++)
#pragma unroll
        for (int j = 0; j < 8; j++)
#pragma unroll
            for (int c = 0; c < 4; c++) acc[i][j][c] = 0.f;

    for (int kc = 0; kc < 24; kc++) {
        if (kc) __syncthreads();
        for (int i = t; i < 2048; i += 128) {
            int row = i >> 4, c16 = i & 15;
            uint32_t o = sw_off(row, c16);
            const float* src = Pp + (size_t)row * Nn + kc * 128 + c16 * 8;
            float4 f0 = reinterpret_cast<const float4*>(src)[0];
            float4 f1 = reinterpret_cast<const float4*>(src)[1];
            float pv[8] = {f0.x, f0.y, f0.z, f0.w, f1.x, f1.y, f1.z, f1.w};
            unsigned short hs[8], ls[8];
#pragma unroll
            for (int j = 0; j < 8; j++) {
                __nv_bfloat16 hb = __float2bfloat16_rn(pv[j]);
                float rem = pv[j] - __bfloat162float(hb);
                hs[j] = __bfloat16_as_ushort(hb);
                ls[j] = __bfloat16_as_ushort(__float2bfloat16_rn(rem));
            }
            uint4 hq, lq;
            hq.x = (uint32_t)hs[0] | ((uint32_t)hs[1] << 16);
            hq.y = (uint32_t)hs[2] | ((uint32_t)hs[3] << 16);
            hq.z = (uint32_t)hs[4] | ((uint32_t)hs[5] << 16);
            hq.w = (uint32_t)hs[6] | ((uint32_t)hs[7] << 16);
            lq.x = (uint32_t)ls[0] | ((uint32_t)ls[1] << 16);
            lq.y = (uint32_t)ls[2] | ((uint32_t)ls[3] << 16);
            lq.z = (uint32_t)ls[4] | ((uint32_t)ls[5] << 16);
            lq.w = (uint32_t)ls[6] | ((uint32_t)ls[7] << 16);
            *reinterpret_cast<uint4*>(smem + o) = hq;
            *reinterpret_cast<uint4*>(smem + PLANE + o) = lq;
            size_t g = (size_t)row * Nn + kc * 128 + c16 * 8;   // row = d
            *reinterpret_cast<uint4*>(smem + 2 * PLANE + o) = *reinterpret_cast<const uint4*>(vh + g);
            *reinterpret_cast<uint4*>(smem + 3 * PLANE + o) = *reinterpret_cast<const uint4*>(vl + g);
        }
        __syncthreads();

#pragma unroll
        for (int kk = 0; kk < 8; kk++) {
            const int arow = (lane & 15), ach = kk * 2 + (lane >> 4);
            uint32_t A0[4][4], A1[4][4], B[8][2];
#pragma unroll
            for (int mi = 0; mi < 4; mi++) {
                int row = m0 + mi * 16 + arow;
                ldsm_x4(A0[mi][0], A0[mi][1], A0[mi][2], A0[mi][3], sb + sw_off(row, ach));
                ldsm_x4(A1[mi][0], A1[mi][1], A1[mi][2], A1[mi][3], sb + PLANE + sw_off(row, ach));
            }
#pragma unroll
            for (int nj = 0; nj < 4; nj++) {
                int row = n0 + nj * 16 + arow;
                uint32_t r0, r1, r2, r3;
                ldsm_x4(r0, r1, r2, r3, sb + 2 * PLANE + sw_off(row, ach));
                B[nj * 2][0] = r0; B[nj * 2][1] = r2;
                B[nj * 2 + 1][0] = r1; B[nj * 2 + 1][1] = r3;
            }
#pragma unroll
            for (int mi = 0; mi < 4; mi++)
#pragma unroll
                for (int ni = 0; ni < 8; ni++) {
                    mma_bf16(acc[mi][ni], A0[mi], B[ni]);   // Ph*Vh
                    mma_bf16(acc[mi][ni], A1[mi], B[ni]);   // Pl*Vh
                }
#pragma unroll
            for (int nj = 0; nj < 4; nj++) {
                int row = n0 + nj * 16 + arow;
                uint32_t r0, r1, r2, r3;
                ldsm_x4(r0, r1, r2, r3, sb + 3 * PLANE + sw_off(row, ach));
                B[nj * 2][0] = r0; B[nj * 2][1] = r2;
                B[nj * 2 + 1][0] = r1; B[nj * 2 + 1][1] = r3;
            }
#pragma unroll
            for (int mi = 0; mi < 4; mi++)
#pragma unroll
                for (int ni = 0; ni < 8; ni++)
                    mma_bf16(acc[mi][ni], A0[mi], B[ni]);   // Ph*Vl
        }
    }

    float* O = out + (size_t)h * Nn * D;
#pragma unroll
    for (int mi = 0; mi < 4; mi++) {
#pragma unroll
        for (int nj = 0; nj < 8; nj++) {
            int r = bm + m0 + mi * 16 + (lane >> 2);
            int c = n0 + nj * 8 + (lane & 3) * 2;
            float2 v01 = make_float2(acc[mi][nj][0], acc[mi][nj][1]);
            float2 v23 = make_float2(acc[mi][nj][2], acc[mi][nj][3]);
            *reinterpret_cast<float2*>(&O[(size_t)r * D + c]) = v01;
            *reinterpret_cast<float2*>(&O[(size_t)(r + 8) * D + c]) = v23;
        }
    }
}

// =============================================================================
// K5: top-896 radix select + threefry random mask + compaction (validated)
// =============================================================================
__global__ __launch_bounds__(256) void select_kernel() {
    const int hg = blockIdx.x;
    const float* cs = g_cs + hg * Nn;
    const int t = threadIdx.x;

    __shared__ unsigned keys[Nn];
    __shared__ unsigned hist[256];
    __shared__ unsigned char mk[Nn];
    __shared__ int scan[256];
    __shared__ unsigned sh_prefix, sh_need;
    __shared__ int base_;

    for (int j = t; j < Nn; j += 256) {
        unsigned u = __float_as_uint(cs[j]);
        keys[j] = (u & 0x80000000u) ? ~u : (u | 0x80000000u);
        mk[j] = 0;
    }
    __syncthreads();

    unsigned prefix = 0, kneed = TOPK;
    for (int shift = 24; shift >= 0; shift -= 8) {
        hist[t] = 0;
        __syncthreads();
        const unsigned himask = (shift == 24) ? 0u : (0xFFFFFFFFu << (shift + 8));
        for (int j = t; j < Nn; j += 256) {
            unsigned u = keys[j];
            if (((u ^ prefix) & himask) == 0)
                atomicAdd(&hist[(u >> shift) & 255u], 1u);
        }
        __syncthreads();
        if (t == 0) {
            unsigned cum = 0; int b = 255;
            for (; b > 0; b--) {
                if (cum + hist[b] >= kneed) break;
                cum += hist[b];
            }
            sh_prefix = prefix | ((unsigned)b << shift);
            sh_need   = kneed - cum;
        }
        __syncthreads();
        prefix = sh_prefix; kneed = sh_need;
        __syncthreads();
    }
    const unsigned T = prefix;

    for (int j = t; j < Nn; j += 256)
        if (keys[j] > T) mk[j] = 1;
    __syncthreads();
    if (t == 0) {
        int need = (int)kneed;
        for (int j = 0; j < Nn && need > 0; j++)
            if (keys[j] == T) { mk[j] = 1; need--; }
    }
    __syncthreads();

    uint2 hk = tf2x32(0u, 1u, 0u, 0u);
    uint2 lk = tf2x32(0u, 1u, 0u, 1u);
    for (int j = t; j < Nn; j += 256) {
        unsigned f = (unsigned)(hg * Nn + j);
        unsigned hi = tf_bits32(hk.x, hk.y, f);
        unsigned lo = tf_bits32(lk.x, lk.y, f);
        unsigned off = ((hi % 100u) * 96u + (lo % 100u)) % 100u;
        if (off == 0u) mk[j] = 1;
    }
    __syncthreads();

    if (t == 0) base_ = 0;
    __syncthreads();
    for (int j0 = 0; j0 < Nn; j0 += 256) {
        int flag = mk[j0 + t];
        scan[t] = flag;
        __syncthreads();
        for (int s = 1; s < 256; s <<= 1) {
            int v = (t >= s) ? scan[t - s] : 0;
            __syncthreads();
            scan[t] += v;
            __syncthreads();
        }
        int incl = scan[t];
        if (flag) g_idx[hg * MAXL + base_ + incl - 1] = j0 + t;
        __syncthreads();
        if (t == 255) base_ += incl;
        __syncthreads();
    }
    if (t == 0) g_cnt[hg] = base_;
}

// =============================================================================
// K6: sparse attention + subtraction (fp32, validated)
// =============================================================================
__global__ __launch_bounds__(256) void sparse_kernel(const float* __restrict__ v,
                                                     float* __restrict__ out) {
    const int h = blockIdx.z, g = blockIdx.y, rc = blockIdx.x;
    const int hg = h * G + g;
    const int row0 = g * BMQ + rc * 64;
    const float* P = g_S + (size_t)h * Nn * Nn;
    const float* V = v + (size_t)h * Nn * D;
    const int L = g_cnt[hg];
    const int* lst = g_idx + hg * MAXL;

    __shared__ float Ps[64][17];
    __shared__ float Vs[16][128];
    __shared__ int   sIdx[16];
    __shared__ float sden[64];

    const int t = threadIdx.x;
    const int tx = t & 15, ty = t >> 4;
    const int m0 = ty * 4, n0 = tx * 8;

    float acc[4][8];
#pragma unroll
    for (int i = 0; i < 4; i++)
#pragma unroll
        for (int j = 0; j < 8; j++) acc[i][j] = 0.f;
    float den[4] = {0.f, 0.f, 0.f, 0.f};

    for (int l0 = 0; l0 < L; l0 += 16) {
        const int nl = min(16, L - l0);
        if (t < 16) sIdx[t] = (t < nl) ? lst[l0 + t] : -1;
        __syncthreads();
#pragma unroll
        for (int it = 0; it < 4; it++) {
            int e = it * 256 + t;
            int r = e & 63, c = e >> 6;
            int col = sIdx[c];
            Ps[r][c] = (col >= 0) ? P[(size_t)(row0 + r) * Nn + col] : 0.f;
        }
#pragma unroll
        for (int it = 0; it < 2; it++) {
            int e = it * 256 + t;
            int kk = e >> 5, d4 = e & 31;
            int col = sIdx[kk];
            float4 val = (col >= 0)
                ? *reinterpret_cast<const float4*>(&V[(size_t)col * D + d4 * 4])
                : make_float4(0.f, 0.f, 0.f, 0.f);
            *reinterpret_cast<float4*>(&Vs[kk][d4 * 4]) = val;
        }
        __syncthreads();
#pragma unroll
        for (int kk = 0; kk < 16; kk++) {
            float a[4], b[8];
#pragma unroll
            for (int i = 0; i < 4; i++) a[i] = Ps[m0 + i][kk];
#pragma unroll
            for (int j = 0; j < 8; j++) b[j] = Vs[kk][n0 + j];
#pragma unroll
            for (int i = 0; i < 4; i++)
#pragma unroll
                for (int j = 0; j < 8; j++) acc[i][j] += a[i] * b[j];
            if (tx == 0) {
#pragma unroll
                for (int i = 0; i < 4; i++) den[i] += a[i];
            }
        }
        __syncthreads();
    }

    if (tx == 0) {
#pragma unroll
        for (int i = 0; i < 4; i++) sden[m0 + i] = den[i];
    }
    __syncthreads();

    const size_t obase = (size_t)h * Nn * D;
    float* out2 = out + (size_t)H * Nn * D;
#pragma unroll
    for (int i = 0; i < 4; i++) {
        const int r = row0 + m0 + i;
        const float dinv = 1.f / sden[m0 + i];
#pragma unroll
        for (int j = 0; j < 8; j++) {
            const int dc = n0 + j;
            float o_ = out[obase + (size_t)r * D + dc];
            out2[obase + (size_t)r * D + dc] = o_ - acc[i][j] * dinv;
        }
    }
}

// =============================================================================
extern "C" void kernel_launch(void* const* d_in, const int* in_sizes, int n_in,
                              void* d_out, int out_size) {
    const float* q = (const float*)d_in[0];
    const float* k = (const float*)d_in[1];
    const float* v = (const float*)d_in[2];
    float* out = (float*)d_out;

    const int SMEM_QK = 6 * PLANE;   // 192 KB
    const int SMEM_PV = 4 * PLANE;   // 128 KB
    cudaFuncSetAttribute(qk_mma_kernel, cudaFuncAttributeMaxDynamicSharedMemorySize, SMEM_QK);
    cudaFuncSetAttribute(pv_mma_kernel, cudaFuncAttributeMaxDynamicSharedMemorySize, SMEM_PV);

    split_qk_kernel<<<dim3(9216, 2), 256>>>(q, k);
    vtrans_kernel<<<dim3(Nn / 32, D / 32, H), dim3(32, 8)>>>(v);
    qk_mma_kernel<<<dim3(24, 24, H), 128, SMEM_QK>>>();
    softmax_kernel<<<dim3(Nn, H), 256>>>();
    cs_kernel<<<dim3(Nn / 256, G, H), 256>>>();
    pv_mma_kernel<<<dim3(24, 1, H), 128, SMEM_PV>>>(out);
    select_kernel<<<HG, 256>>>();
    sparse_kernel<<<dim3(3, G, H), 256>>>(v, out);
}

// round 10
// speedup vs baseline: 1.1258x; 1.1074x over previous
#include <cuda_runtime.h>
#include <cuda_bf16.h>
#include <stdint.h>
#include <math.h>

// Problem constants
#define H   24
#define Nn  3072
#define D   128
#define BMQ 192
#define G   16
#define HG  (H * G)
#define TOPK 896

// ---------------- device scratch (static; no runtime allocation) -------------
__device__ float g_S[(size_t)H * Nn * Nn];       // S then P (fp32, in place)
__device__ float g_cs[HG * Nn];
__device__ uint32_t g_mask[HG * 96];             // per-group column bitmask (3072 bits)
// 3-way split planes for Q and K (a + b + c, each bf16)
__device__ __nv_bfloat16 g_qa[(size_t)H * Nn * D];
__device__ __nv_bfloat16 g_qb[(size_t)H * Nn * D];
__device__ __nv_bfloat16 g_qc[(size_t)H * Nn * D];
__device__ __nv_bfloat16 g_ka[(size_t)H * Nn * D];
__device__ __nv_bfloat16 g_kb[(size_t)H * Nn * D];
__device__ __nv_bfloat16 g_kc[(size_t)H * Nn * D];
// 2-way split V^T planes [h][d][k]
__device__ __nv_bfloat16 g_vth[(size_t)H * D * Nn];
__device__ __nv_bfloat16 g_vtl[(size_t)H * D * Nn];

// ---------------- helpers ----------------------------------------------------
__device__ __forceinline__ uint32_t smem_to_u32(const void* p) {
    uint32_t a;
    asm("{ .reg .u64 t; cvta.to.shared.u64 t, %1; cvt.u32.u64 %0, t; }" : "=r"(a) : "l"(p));
    return a;
}

__device__ __forceinline__ void ldsm_x4(uint32_t& r0, uint32_t& r1, uint32_t& r2,
                                        uint32_t& r3, uint32_t addr) {
    asm volatile("ldmatrix.sync.aligned.m8n8.x4.shared.b16 {%0,%1,%2,%3}, [%4];"
                 : "=r"(r0), "=r"(r1), "=r"(r2), "=r"(r3) : "r"(addr));
}

__device__ __forceinline__ void mma_bf16(float* c, const uint32_t* a, const uint32_t* b) {
    asm volatile(
        "mma.sync.aligned.m16n8k16.row.col.f32.bf16.bf16.f32 "
        "{%0,%1,%2,%3}, {%4,%5,%6,%7}, {%8,%9}, {%0,%1,%2,%3};"
        : "+f"(c[0]), "+f"(c[1]), "+f"(c[2]), "+f"(c[3])
        : "r"(a[0]), "r"(a[1]), "r"(a[2]), "r"(a[3]), "r"(b[0]), "r"(b[1]));
}

// smem tile: 128 rows x 256B (128 bf16), 16B chunks xor-swizzled by row%8
__device__ __forceinline__ uint32_t sw_off(int row, int c16) {
    return (uint32_t)(row * 256 + ((c16 ^ (row & 7)) << 4));
}

#define PLANE 32768

// ---------------- threefry2x32 ----------------------------------------------
#define TF_ROUND(x0, x1, r) { x0 += x1; x1 = (x1 << r) | (x1 >> (32 - r)); x1 ^= x0; }
__device__ __forceinline__ uint2 tf2x32(unsigned k0, unsigned k1, unsigned c0, unsigned c1) {
    unsigned ks2 = k0 ^ k1 ^ 0x1BD11BDAu;
    unsigned x0 = c0 + k0, x1 = c1 + k1;
    TF_ROUND(x0, x1, 13) TF_ROUND(x0, x1, 15) TF_ROUND(x0, x1, 26) TF_ROUND(x0, x1, 6)
    x0 += k1;  x1 += ks2 + 1u;
    TF_ROUND(x0, x1, 17) TF_ROUND(x0, x1, 29) TF_ROUND(x0, x1, 16) TF_ROUND(x0, x1, 24)
    x0 += ks2; x1 += k0 + 2u;
    TF_ROUND(x0, x1, 13) TF_ROUND(x0, x1, 15) TF_ROUND(x0, x1, 26) TF_ROUND(x0, x1, 6)
    x0 += k0;  x1 += k1 + 3u;
    TF_ROUND(x0, x1, 17) TF_ROUND(x0, x1, 29) TF_ROUND(x0, x1, 16) TF_ROUND(x0, x1, 24)
    x0 += k1;  x1 += ks2 + 4u;
    TF_ROUND(x0, x1, 13) TF_ROUND(x0, x1, 15) TF_ROUND(x0, x1, 26) TF_ROUND(x0, x1, 6)
    x0 += ks2; x1 += k0 + 5u;
    return make_uint2(x0, x1);
}
__device__ __forceinline__ unsigned tf_bits32(unsigned k0, unsigned k1, unsigned f) {
    uint2 o = tf2x32(k0, k1, 0u, f);
    return o.x ^ o.y;
}

// =============================================================================
// K0a: split q,k into 3 bf16 planes (a + b + c)
// =============================================================================
__global__ __launch_bounds__(256) void split_qk_kernel(const float* __restrict__ q,
                                                       const float* __restrict__ k) {
    const int which = blockIdx.y;
    const float* src = which ? k : q;
    __nv_bfloat16* da = which ? g_ka : g_qa;
    __nv_bfloat16* db = which ? g_kb : g_qb;
    __nv_bfloat16* dc = which ? g_kc : g_qc;
    size_t i = (size_t)blockIdx.x * 256 + threadIdx.x;   // float4 index
    float4 x = reinterpret_cast<const float4*>(src)[i];
    float v[4] = {x.x, x.y, x.z, x.w};
    unsigned short as_[4], bs[4], cs_[4];
#pragma unroll
    for (int j = 0; j < 4; j++) {
        __nv_bfloat16 ab = __float2bfloat16_rn(v[j]);
        float r1 = v[j] - __bfloat162float(ab);
        __nv_bfloat16 bb = __float2bfloat16_rn(r1);
        float r2 = r1 - __bfloat162float(bb);
        __nv_bfloat16 cb = __float2bfloat16_rn(r2);
        as_[j] = __bfloat16_as_ushort(ab);
        bs[j]  = __bfloat16_as_ushort(bb);
        cs_[j] = __bfloat16_as_ushort(cb);
    }
    uint2 av, bv, cv;
    av.x = (uint32_t)as_[0] | ((uint32_t)as_[1] << 16);
    av.y = (uint32_t)as_[2] | ((uint32_t)as_[3] << 16);
    bv.x = (uint32_t)bs[0]  | ((uint32_t)bs[1] << 16);
    bv.y = (uint32_t)bs[2]  | ((uint32_t)bs[3] << 16);
    cv.x = (uint32_t)cs_[0] | ((uint32_t)cs_[1] << 16);
    cv.y = (uint32_t)cs_[2] | ((uint32_t)cs_[3] << 16);
    reinterpret_cast<uint2*>(da)[i] = av;
    reinterpret_cast<uint2*>(db)[i] = bv;
    reinterpret_cast<uint2*>(dc)[i] = cv;
}

// =============================================================================
// K0b: transpose + split V -> VT hi/lo planes [h][d][k]
// =============================================================================
__global__ void vtrans_kernel(const float* __restrict__ v) {
    const int h = blockIdx.z, k0 = blockIdx.x * 32, d0 = blockIdx.y * 32;
    __shared__ float tile[32][33];
    const int tx = threadIdx.x, ty = threadIdx.y;
    const float* V = v + (size_t)h * Nn * D;
    for (int r = ty; r < 32; r += 8)
        tile[r][tx] = V[(size_t)(k0 + r) * D + d0 + tx];
    __syncthreads();
    for (int r = ty; r < 32; r += 8) {
        float val = tile[tx][r];
        __nv_bfloat16 hb = __float2bfloat16_rn(val);
        float rem = val - __bfloat162float(hb);
        __nv_bfloat16 lb = __float2bfloat16_rn(rem);
        size_t o = (size_t)h * D * Nn + (size_t)(d0 + r) * Nn + k0 + tx;
        g_vth[o] = hb;
        g_vtl[o] = lb;
    }
}

// =============================================================================
// K1: S = scale * Q K^T via mma.sync bf16, 3-way split (6 products) [validated]
// =============================================================================
__global__ __launch_bounds__(128) void qk_mma_kernel() {
    extern __shared__ char smem[];
    const uint32_t sb = smem_to_u32(smem);
    const int t = threadIdx.x, lane = t & 31, wid = t >> 5;
    const int h = blockIdx.z, bm = blockIdx.x * 128, bn = blockIdx.y * 128;

    {   // fill 6 planes
        const size_t qg = (size_t)h * Nn * D + (size_t)bm * D;
        const size_t kg = (size_t)h * Nn * D + (size_t)bn * D;
        const __nv_bfloat16* s0 = g_qa + qg;
        const __nv_bfloat16* s1 = g_qb + qg;
        const __nv_bfloat16* s2 = g_qc + qg;
        const __nv_bfloat16* s3 = g_ka + kg;
        const __nv_bfloat16* s4 = g_kb + kg;
        const __nv_bfloat16* s5 = g_kc + kg;
        for (int i = t; i < 2048; i += 128) {
            int row = i >> 4, c16 = i & 15;
            uint32_t o = sw_off(row, c16);
            size_t g = (size_t)row * D + c16 * 8;
            *reinterpret_cast<uint4*>(smem + o)             = *reinterpret_cast<const uint4*>(s0 + g);
            *reinterpret_cast<uint4*>(smem + PLANE + o)     = *reinterpret_cast<const uint4*>(s1 + g);
            *reinterpret_cast<uint4*>(smem + 2 * PLANE + o) = *reinterpret_cast<const uint4*>(s2 + g);
            *reinterpret_cast<uint4*>(smem + 3 * PLANE + o) = *reinterpret_cast<const uint4*>(s3 + g);
            *reinterpret_cast<uint4*>(smem + 4 * PLANE + o) = *reinterpret_cast<const uint4*>(s4 + g);
            *reinterpret_cast<uint4*>(smem + 5 * PLANE + o) = *reinterpret_cast<const uint4*>(s5 + g);
        }
    }
    __syncthreads();

    const int m0 = (wid >> 1) * 64, n0 = (wid & 1) * 64;
    float acc[4][8][4];
#pragma unroll
    for (int i = 0; i < 4; i++)
#pragma unroll
        for (int j = 0; j < 8; j++)
#pragma unroll
            for (int c = 0; c < 4; c++) acc[i][j][c] = 0.f;

#pragma unroll
    for (int kk = 0; kk < 8; kk++) {
        const int arow = (lane & 15), ach = kk * 2 + (lane >> 4);
        uint32_t A[4][4], B[8][2];
#pragma unroll
        for (int bi = 0; bi < 3; bi++) {
#pragma unroll
            for (int nj = 0; nj < 4; nj++) {
                int row = n0 + nj * 16 + arow;
                uint32_t r0, r1, r2, r3;
                ldsm_x4(r0, r1, r2, r3, sb + (3 + bi) * PLANE + sw_off(row, ach));
                B[nj * 2][0] = r0; B[nj * 2][1] = r2;
                B[nj * 2 + 1][0] = r1; B[nj * 2 + 1][1] = r3;
            }
            const int nA = (bi == 0) ? 3 : (bi == 1) ? 2 : 1;
#pragma unroll
            for (int ai = 0; ai < 3; ai++) {
                if (ai >= nA) continue;
#pragma unroll
                for (int mi = 0; mi < 4; mi++) {
                    int row = m0 + mi * 16 + arow;
                    ldsm_x4(A[mi][0], A[mi][1], A[mi][2], A[mi][3],
                            sb + ai * PLANE + sw_off(row, ach));
                }
#pragma unroll
                for (int mi = 0; mi < 4; mi++)
#pragma unroll
                    for (int ni = 0; ni < 8; ni++)
                        mma_bf16(acc[mi][ni], A[mi], B[ni]);
            }
        }
    }

    const float scale = 0.08838834764831845f;
    float* S = g_S + (size_t)h * Nn * Nn;
#pragma unroll
    for (int mi = 0; mi < 4; mi++) {
#pragma unroll
        for (int nj = 0; nj < 8; nj++) {
            int r = bm + m0 + mi * 16 + (lane >> 2);
            int c = bn + n0 + nj * 8 + (lane & 3) * 2;
            float2 v01 = make_float2(acc[mi][nj][0] * scale, acc[mi][nj][1] * scale);
            float2 v23 = make_float2(acc[mi][nj][2] * scale, acc[mi][nj][3] * scale);
            *reinterpret_cast<float2*>(&S[(size_t)r * Nn + c]) = v01;
            *reinterpret_cast<float2*>(&S[(size_t)(r + 8) * Nn + c]) = v23;
        }
    }
}

// =============================================================================
// K2: fused row softmax + group column sums
//     grid (G, H), 256 threads; rows register-resident (12 floats/thread)
// =============================================================================
__global__ __launch_bounds__(256) void softmax_cs_kernel() {
    const int g = blockIdx.x, h = blockIdx.y;
    const int t = threadIdx.x, lane = t & 31, warp = t >> 5;

    __shared__ float colsum[Nn];
    __shared__ float redm[8];
    __shared__ float reds[8];

    for (int j = t; j < Nn; j += 256) colsum[j] = 0.f;
    __syncthreads();

    for (int r = 0; r < BMQ; r++) {
        const int row = g * BMQ + r;
        float* Srow = g_S + (size_t)h * Nn * Nn + (size_t)row * Nn;
        float4* S4 = reinterpret_cast<float4*>(Srow);

        float4 v0 = S4[t], v1 = S4[t + 256], v2 = S4[t + 512];
        float mx = fmaxf(fmaxf(fmaxf(v0.x, v0.y), fmaxf(v0.z, v0.w)),
                   fmaxf(fmaxf(fmaxf(v1.x, v1.y), fmaxf(v1.z, v1.w)),
                         fmaxf(fmaxf(v2.x, v2.y), fmaxf(v2.z, v2.w))));
#pragma unroll
        for (int o = 16; o > 0; o >>= 1) mx = fmaxf(mx, __shfl_xor_sync(0xffffffffu, mx, o));
        if (lane == 0) redm[warp] = mx;
        __syncthreads();
        float rowmax = redm[0];
#pragma unroll
        for (int w = 1; w < 8; w++) rowmax = fmaxf(rowmax, redm[w]);

        v0.x = expf(v0.x - rowmax); v0.y = expf(v0.y - rowmax);
        v0.z = expf(v0.z - rowmax); v0.w = expf(v0.w - rowmax);
        v1.x = expf(v1.x - rowmax); v1.y = expf(v1.y - rowmax);
        v1.z = expf(v1.z - rowmax); v1.w = expf(v1.w - rowmax);
        v2.x = expf(v2.x - rowmax); v2.y = expf(v2.y - rowmax);
        v2.z = expf(v2.z - rowmax); v2.w = expf(v2.w - rowmax);
        float sum = (v0.x + v0.y + v0.z + v0.w) + (v1.x + v1.y + v1.z + v1.w)
                  + (v2.x + v2.y + v2.z + v2.w);
#pragma unroll
        for (int o = 16; o > 0; o >>= 1) sum += __shfl_xor_sync(0xffffffffu, sum, o);
        if (lane == 0) reds[warp] = sum;
        __syncthreads();
        float tot = reds[0];
#pragma unroll
        for (int w = 1; w < 8; w++) tot += reds[w];
        const float inv = 1.f / tot;

        v0.x *= inv; v0.y *= inv; v0.z *= inv; v0.w *= inv;
        v1.x *= inv; v1.y *= inv; v1.z *= inv; v1.w *= inv;
        v2.x *= inv; v2.y *= inv; v2.z *= inv; v2.w *= inv;
        S4[t] = v0; S4[t + 256] = v1; S4[t + 512] = v2;
        int j0 = t * 4, j1 = (t + 256) * 4, j2 = (t + 512) * 4;
        colsum[j0] += v0.x; colsum[j0 + 1] += v0.y; colsum[j0 + 2] += v0.z; colsum[j0 + 3] += v0.w;
        colsum[j1] += v1.x; colsum[j1 + 1] += v1.y; colsum[j1 + 2] += v1.z; colsum[j1 + 3] += v1.w;
        colsum[j2] += v2.x; colsum[j2 + 1] += v2.y; colsum[j2 + 2] += v2.z; colsum[j2 + 3] += v2.w;
        __syncthreads();   // protect redm/reds for next row
    }

    float* cs = g_cs + (h * G + g) * Nn;
    for (int j = t; j < Nn; j += 256) cs[j] = colsum[j];
}

// =============================================================================
// K3: top-896 radix select + threefry random mask -> bitmask
// =============================================================================
__global__ __launch_bounds__(256) void select_kernel() {
    const int hg = blockIdx.x;
    const float* cs = g_cs + hg * Nn;
    const int t = threadIdx.x;

    __shared__ unsigned keys[Nn];
    __shared__ unsigned hist[256];
    __shared__ unsigned char mk[Nn];
    __shared__ unsigned sh_prefix, sh_need;

    for (int j = t; j < Nn; j += 256) {
        unsigned u = __float_as_uint(cs[j]);
        keys[j] = (u & 0x80000000u) ? ~u : (u | 0x80000000u);
        mk[j] = 0;
    }
    __syncthreads();

    unsigned prefix = 0, kneed = TOPK;
    for (int shift = 24; shift >= 0; shift -= 8) {
        hist[t] = 0;
        __syncthreads();
        const unsigned himask = (shift == 24) ? 0u : (0xFFFFFFFFu << (shift + 8));
        for (int j = t; j < Nn; j += 256) {
            unsigned u = keys[j];
            if (((u ^ prefix) & himask) == 0)
                atomicAdd(&hist[(u >> shift) & 255u], 1u);
        }
        __syncthreads();
        if (t == 0) {
            unsigned cum = 0; int b = 255;
            for (; b > 0; b--) {
                if (cum + hist[b] >= kneed) break;
                cum += hist[b];
            }
            sh_prefix = prefix | ((unsigned)b << shift);
            sh_need   = kneed - cum;
        }
        __syncthreads();
        prefix = sh_prefix; kneed = sh_need;
        __syncthreads();
    }
    const unsigned T = prefix;

    for (int j = t; j < Nn; j += 256)
        if (keys[j] > T) mk[j] = 1;
    __syncthreads();
    if (t == 0) {
        int need = (int)kneed;
        for (int j = 0; j < Nn && need > 0; j++)
            if (keys[j] == T) { mk[j] = 1; need--; }
    }
    __syncthreads();

    uint2 hk = tf2x32(0u, 1u, 0u, 0u);
    uint2 lk = tf2x32(0u, 1u, 0u, 1u);
    for (int j = t; j < Nn; j += 256) {
        unsigned f = (unsigned)(hg * Nn + j);
        unsigned hi = tf_bits32(hk.x, hk.y, f);
        unsigned lo = tf_bits32(lk.x, lk.y, f);
        unsigned off = ((hi % 100u) * 96u + (lo % 100u)) % 100u;
        if (off == 0u) mk[j] = 1;
    }
    __syncthreads();

    // pack to bitmask words
    if (t < 96) {
        unsigned w = 0;
#pragma unroll
        for (int b = 0; b < 32; b++)
            if (mk[t * 32 + b]) w |= (1u << b);
        g_mask[hg * 96 + t] = w;
    }
}

// =============================================================================
// K4: fused PV — dense O, masked SP, out2 = O - SP/den; one pass over P
//     256 threads, 8 warps, warp tile 64(m) x 32(d)
//     smem planes: 0:Ph 1:Pl 2:Pmh 3:Pml 4:Vh 5:Vl, then masks + den
// =============================================================================
__global__ __launch_bounds__(256) void pv_fused_kernel(float* __restrict__ out) {
    extern __shared__ char smem[];
    const uint32_t sb = smem_to_u32(smem);
    uint32_t* mskS = reinterpret_cast<uint32_t*>(smem + 6 * PLANE);   // [2][96]
    float*   den  = reinterpret_cast<float*>(smem + 6 * PLANE + 768); // [128]
    const int t = threadIdx.x, lane = t & 31, wid = t >> 5;
    const int h = blockIdx.z, bm = blockIdx.x * 128;

    const int ga = bm / BMQ;
    const int gb = (bm + 127) / BMQ;
    if (t < 128) den[t] = 0.f;
    if (t >= 128 && t < 224) mskS[t - 128] = g_mask[(h * G + ga) * 96 + (t - 128)];
    if (t >= 224 && t < 256) {
        // load gb mask words 0..95 with 32 threads x 3
        for (int w = t - 224; w < 96; w += 32)
            mskS[96 + w] = g_mask[(h * G + gb) * 96 + w];
    }
    __syncthreads();

    const float* Pp = g_S + (size_t)h * Nn * Nn + (size_t)bm * Nn;
    const __nv_bfloat16* vh = g_vth + (size_t)h * D * Nn;
    const __nv_bfloat16* vl = g_vtl + (size_t)h * D * Nn;

    const int m0 = (wid >> 2) * 64, n0 = (wid & 3) * 32;
    float accD[4][4][4], accM[4][4][4];
#pragma unroll
    for (int i = 0; i < 4; i++)
#pragma unroll
        for (int j = 0; j < 4; j++)
#pragma unroll
            for (int c = 0; c < 4; c++) { accD[i][j][c] = 0.f; accM[i][j][c] = 0.f; }

    for (int kc = 0; kc < 24; kc++) {
        if (kc) __syncthreads();
        for (int i = t; i < 2048; i += 256) {
            int row = i >> 4, c16 = i & 15;
            uint32_t o = sw_off(row, c16);
            const int colbase = kc * 128 + c16 * 8;
            const int gsel = ((bm + row) >= (ga + 1) * BMQ) ? 1 : 0;
            const uint32_t mbits = mskS[gsel * 96 + (colbase >> 5)] >> (colbase & 31);

            const float* src = Pp + (size_t)row * Nn + colbase;
            float4 f0 = reinterpret_cast<const float4*>(src)[0];
            float4 f1 = reinterpret_cast<const float4*>(src)[1];
            float pv[8] = {f0.x, f0.y, f0.z, f0.w, f1.x, f1.y, f1.z, f1.w};
            unsigned short hs[8], ls[8], mh[8], ml[8];
            float dsum = 0.f;
#pragma unroll
            for (int j = 0; j < 8; j++) {
                __nv_bfloat16 hb = __float2bfloat16_rn(pv[j]);
                float rem = pv[j] - __bfloat162float(hb);
                hs[j] = __bfloat16_as_ushort(hb);
                ls[j] = __bfloat16_as_ushort(__float2bfloat16_rn(rem));
                if ((mbits >> j) & 1u) { mh[j] = hs[j]; ml[j] = ls[j]; dsum += pv[j]; }
                else { mh[j] = 0; ml[j] = 0; }
            }
            uint4 q;
            q.x = (uint32_t)hs[0] | ((uint32_t)hs[1] << 16);
            q.y = (uint32_t)hs[2] | ((uint32_t)hs[3] << 16);
            q.z = (uint32_t)hs[4] | ((uint32_t)hs[5] << 16);
            q.w = (uint32_t)hs[6] | ((uint32_t)hs[7] << 16);
            *reinterpret_cast<uint4*>(smem + o) = q;
            q.x = (uint32_t)ls[0] | ((uint32_t)ls[1] << 16);
            q.y = (uint32_t)ls[2] | ((uint32_t)ls[3] << 16);
            q.z = (uint32_t)ls[4] | ((uint32_t)ls[5] << 16);
            q.w = (uint32_t)ls[6] | ((uint32_t)ls[7] << 16);
            *reinterpret_cast<uint4*>(smem + PLANE + o) = q;
            q.x = (uint32_t)mh[0] | ((uint32_t)mh[1] << 16);
            q.y = (uint32_t)mh[2] | ((uint32_t)mh[3] << 16);
            q.z = (uint32_t)mh[4] | ((uint32_t)mh[5] << 16);
            q.w = (uint32_t)mh[6] | ((uint32_t)mh[7] << 16);
            *reinterpret_cast<uint4*>(smem + 2 * PLANE + o) = q;
            q.x = (uint32_t)ml[0] | ((uint32_t)ml[1] << 16);
            q.y = (uint32_t)ml[2] | ((uint32_t)ml[3] << 16);
            q.z = (uint32_t)ml[4] | ((uint32_t)ml[5] << 16);
            q.w = (uint32_t)ml[6] | ((uint32_t)ml[7] << 16);
            *reinterpret_cast<uint4*>(smem + 3 * PLANE + o) = q;

            size_t gg = (size_t)row * Nn + colbase;   // row = d for V planes
            *reinterpret_cast<uint4*>(smem + 4 * PLANE + o) = *reinterpret_cast<const uint4*>(vh + gg);
            *reinterpret_cast<uint4*>(smem + 5 * PLANE + o) = *reinterpret_cast<const uint4*>(vl + gg);
            if (dsum != 0.f) atomicAdd(&den[row], dsum);
        }
        __syncthreads();

#pragma unroll
        for (int kk = 0; kk < 8; kk++) {
            const int arow = (lane & 15), ach = kk * 2 + (lane >> 4);
            uint32_t Bh[4][2], Bl[4][2];
#pragma unroll
            for (int nj = 0; nj < 2; nj++) {
                int row = n0 + nj * 16 + arow;
                uint32_t r0, r1, r2, r3;
                ldsm_x4(r0, r1, r2, r3, sb + 4 * PLANE + sw_off(row, ach));
                Bh[nj * 2][0] = r0; Bh[nj * 2][1] = r2;
                Bh[nj * 2 + 1][0] = r1; Bh[nj * 2 + 1][1] = r3;
                ldsm_x4(r0, r1, r2, r3, sb + 5 * PLANE + sw_off(row, ach));
                Bl[nj * 2][0] = r0; Bl[nj * 2][1] = r2;
                Bl[nj * 2 + 1][0] = r1; Bl[nj * 2 + 1][1] = r3;
            }
#pragma unroll
            for (int mi = 0; mi < 4; mi++) {
                int row = m0 + mi * 16 + arow;
                uint32_t Ah[4], Al[4], Amh[4], Aml[4];
                ldsm_x4(Ah[0], Ah[1], Ah[2], Ah[3], sb + sw_off(row, ach));
                ldsm_x4(Al[0], Al[1], Al[2], Al[3], sb + PLANE + sw_off(row, ach));
                ldsm_x4(Amh[0], Amh[1], Amh[2], Amh[3], sb + 2 * PLANE + sw_off(row, ach));
                ldsm_x4(Aml[0], Aml[1], Aml[2], Aml[3], sb + 3 * PLANE + sw_off(row, ach));
#pragma unroll
                for (int n8 = 0; n8 < 4; n8++) {
                    mma_bf16(accD[mi][n8], Ah, Bh[n8]);
                    mma_bf16(accD[mi][n8], Al, Bh[n8]);
                    mma_bf16(accD[mi][n8], Ah, Bl[n8]);
                    mma_bf16(accM[mi][n8], Amh, Bh[n8]);
                    mma_bf16(accM[mi][n8], Aml, Bh[n8]);
                    mma_bf16(accM[mi][n8], Amh, Bl[n8]);
                }
            }
        }
    }
    __syncthreads();

    float* O  = out + (size_t)h * Nn * D;
    float* O2 = out + (size_t)H * Nn * D + (size_t)h * Nn * D;
#pragma unroll
    for (int mi = 0; mi < 4; mi++) {
#pragma unroll
        for (int n8 = 0; n8 < 4; n8++) {
            int rl0 = m0 + mi * 16 + (lane >> 2);
            int rl1 = rl0 + 8;
            int c = n0 + n8 * 8 + (lane & 3) * 2;
            float inv0 = 1.f / den[rl0];
            float inv1 = 1.f / den[rl1];
            float2 d01 = make_float2(accD[mi][n8][0], accD[mi][n8][1]);
            float2 d23 = make_float2(accD[mi][n8][2], accD[mi][n8][3]);
            *reinterpret_cast<float2*>(&O[(size_t)(bm + rl0) * D + c]) = d01;
            *reinterpret_cast<float2*>(&O[(size_t)(bm + rl1) * D + c]) = d23;
            float2 s01 = make_float2(d01.x - accM[mi][n8][0] * inv0,
                                     d01.y - accM[mi][n8][1] * inv0);
            float2 s23 = make_float2(d23.x - accM[mi][n8][2] * inv1,
                                     d23.y - accM[mi][n8][3] * inv1);
            *reinterpret_cast<float2*>(&O2[(size_t)(bm + rl0) * D + c]) = s01;
            *reinterpret_cast<float2*>(&O2[(size_t)(bm + rl1) * D + c]) = s23;
        }
    }
}

// =============================================================================
extern "C" void kernel_launch(void* const* d_in, const int* in_sizes, int n_in,
                              void* d_out, int out_size) {
    const float* q = (const float*)d_in[0];
    const float* k = (const float*)d_in[1];
    const float* v = (const float*)d_in[2];
    float* out = (float*)d_out;

    const int SMEM_QK = 6 * PLANE;             // 192 KB
    const int SMEM_PV = 6 * PLANE + 768 + 512; // 192 KB + mask + den
    cudaFuncSetAttribute(qk_mma_kernel, cudaFuncAttributeMaxDynamicSharedMemorySize, SMEM_QK);
    cudaFuncSetAttribute(pv_fused_kernel, cudaFuncAttributeMaxDynamicSharedMemorySize, SMEM_PV);

    split_qk_kernel<<<dim3(9216, 2), 256>>>(q, k);
    vtrans_kernel<<<dim3(Nn / 32, D / 32, H), dim3(32, 8)>>>(v);
    qk_mma_kernel<<<dim3(24, 24, H), 128, SMEM_QK>>>();
    softmax_cs_kernel<<<dim3(G, H), 256>>>();
    select_kernel<<<HG, 256>>>();
    pv_fused_kernel<<<dim3(24, 1, H), 256, SMEM_PV>>>(out);
}

// round 11
// speedup vs baseline: 1.2827x; 1.1394x over previous
#include <cuda_runtime.h>
#include <cuda_bf16.h>
#include <stdint.h>
#include <math.h>

// Problem constants
#define H   24
#define Nn  3072
#define D   128
#define BMQ 192
#define G   16
#define HG  (H * G)
#define TOPK 896

// ---------------- device scratch (static; no runtime allocation) -------------
__device__ float g_S[(size_t)H * Nn * Nn];       // S (fp32)
__device__ __nv_bfloat16 g_ph[(size_t)H * Nn * Nn];  // P hi plane
__device__ __nv_bfloat16 g_pl[(size_t)H * Nn * Nn];  // P lo plane
__device__ float g_cs[HG * Nn];
__device__ uint32_t g_mask[HG * 96];             // per-group column bitmask
// 3-way split planes for Q and K (a + b + c, each bf16)
__device__ __nv_bfloat16 g_qa[(size_t)H * Nn * D];
__device__ __nv_bfloat16 g_qb[(size_t)H * Nn * D];
__device__ __nv_bfloat16 g_qc[(size_t)H * Nn * D];
__device__ __nv_bfloat16 g_ka[(size_t)H * Nn * D];
__device__ __nv_bfloat16 g_kb[(size_t)H * Nn * D];
__device__ __nv_bfloat16 g_kc[(size_t)H * Nn * D];
// 2-way split V^T planes [h][d][k]
__device__ __nv_bfloat16 g_vth[(size_t)H * D * Nn];
__device__ __nv_bfloat16 g_vtl[(size_t)H * D * Nn];

// ---------------- helpers ----------------------------------------------------
__device__ __forceinline__ uint32_t smem_to_u32(const void* p) {
    uint32_t a;
    asm("{ .reg .u64 t; cvta.to.shared.u64 t, %1; cvt.u32.u64 %0, t; }" : "=r"(a) : "l"(p));
    return a;
}

__device__ __forceinline__ void ldsm_x4(uint32_t& r0, uint32_t& r1, uint32_t& r2,
                                        uint32_t& r3, uint32_t addr) {
    asm volatile("ldmatrix.sync.aligned.m8n8.x4.shared.b16 {%0,%1,%2,%3}, [%4];"
                 : "=r"(r0), "=r"(r1), "=r"(r2), "=r"(r3) : "r"(addr));
}

__device__ __forceinline__ void mma_bf16(float* c, const uint32_t* a, const uint32_t* b) {
    asm volatile(
        "mma.sync.aligned.m16n8k16.row.col.f32.bf16.bf16.f32 "
        "{%0,%1,%2,%3}, {%4,%5,%6,%7}, {%8,%9}, {%0,%1,%2,%3};"
        : "+f"(c[0]), "+f"(c[1]), "+f"(c[2]), "+f"(c[3])
        : "r"(a[0]), "r"(a[1]), "r"(a[2]), "r"(a[3]), "r"(b[0]), "r"(b[1]));
}

// smem tile: 128 rows x 256B (128 bf16), 16B chunks xor-swizzled by row%8
__device__ __forceinline__ uint32_t sw_off(int row, int c16) {
    return (uint32_t)(row * 256 + ((c16 ^ (row & 7)) << 4));
}

#define PLANE 32768

// ---------------- threefry2x32 ----------------------------------------------
#define TF_ROUND(x0, x1, r) { x0 += x1; x1 = (x1 << r) | (x1 >> (32 - r)); x1 ^= x0; }
__device__ __forceinline__ uint2 tf2x32(unsigned k0, unsigned k1, unsigned c0, unsigned c1) {
    unsigned ks2 = k0 ^ k1 ^ 0x1BD11BDAu;
    unsigned x0 = c0 + k0, x1 = c1 + k1;
    TF_ROUND(x0, x1, 13) TF_ROUND(x0, x1, 15) TF_ROUND(x0, x1, 26) TF_ROUND(x0, x1, 6)
    x0 += k1;  x1 += ks2 + 1u;
    TF_ROUND(x0, x1, 17) TF_ROUND(x0, x1, 29) TF_ROUND(x0, x1, 16) TF_ROUND(x0, x1, 24)
    x0 += ks2; x1 += k0 + 2u;
    TF_ROUND(x0, x1, 13) TF_ROUND(x0, x1, 15) TF_ROUND(x0, x1, 26) TF_ROUND(x0, x1, 6)
    x0 += k0;  x1 += k1 + 3u;
    TF_ROUND(x0, x1, 17) TF_ROUND(x0, x1, 29) TF_ROUND(x0, x1, 16) TF_ROUND(x0, x1, 24)
    x0 += k1;  x1 += ks2 + 4u;
    TF_ROUND(x0, x1, 13) TF_ROUND(x0, x1, 15) TF_ROUND(x0, x1, 26) TF_ROUND(x0, x1, 6)
    x0 += ks2; x1 += k0 + 5u;
    return make_uint2(x0, x1);
}
__device__ __forceinline__ unsigned tf_bits32(unsigned k0, unsigned k1, unsigned f) {
    uint2 o = tf2x32(k0, k1, 0u, f);
    return o.x ^ o.y;
}

// =============================================================================
// K0a: split q,k into 3 bf16 planes (a + b + c); also zero g_cs
// =============================================================================
__global__ __launch_bounds__(256) void split_qk_kernel(const float* __restrict__ q,
                                                       const float* __restrict__ k) {
    const int which = blockIdx.y;
    if (which == 0 && blockIdx.x < 4608)
        g_cs[blockIdx.x * 256 + threadIdx.x] = 0.f;
    const float* src = which ? k : q;
    __nv_bfloat16* da = which ? g_ka : g_qa;
    __nv_bfloat16* db = which ? g_kb : g_qb;
    __nv_bfloat16* dc = which ? g_kc : g_qc;
    size_t i = (size_t)blockIdx.x * 256 + threadIdx.x;   // float4 index
    float4 x = reinterpret_cast<const float4*>(src)[i];
    float v[4] = {x.x, x.y, x.z, x.w};
    unsigned short as_[4], bs[4], cs_[4];
#pragma unroll
    for (int j = 0; j < 4; j++) {
        __nv_bfloat16 ab = __float2bfloat16_rn(v[j]);
        float r1 = v[j] - __bfloat162float(ab);
        __nv_bfloat16 bb = __float2bfloat16_rn(r1);
        float r2 = r1 - __bfloat162float(bb);
        __nv_bfloat16 cb = __float2bfloat16_rn(r2);
        as_[j] = __bfloat16_as_ushort(ab);
        bs[j]  = __bfloat16_as_ushort(bb);
        cs_[j] = __bfloat16_as_ushort(cb);
    }
    uint2 av, bv, cv;
    av.x = (uint32_t)as_[0] | ((uint32_t)as_[1] << 16);
    av.y = (uint32_t)as_[2] | ((uint32_t)as_[3] << 16);
    bv.x = (uint32_t)bs[0]  | ((uint32_t)bs[1] << 16);
    bv.y = (uint32_t)bs[2]  | ((uint32_t)bs[3] << 16);
    cv.x = (uint32_t)cs_[0] | ((uint32_t)cs_[1] << 16);
    cv.y = (uint32_t)cs_[2] | ((uint32_t)cs_[3] << 16);
    reinterpret_cast<uint2*>(da)[i] = av;
    reinterpret_cast<uint2*>(db)[i] = bv;
    reinterpret_cast<uint2*>(dc)[i] = cv;
}

// =============================================================================
// K0b: transpose + split V -> VT hi/lo planes [h][d][k]
// =============================================================================
__global__ void vtrans_kernel(const float* __restrict__ v) {
    const int h = blockIdx.z, k0 = blockIdx.x * 32, d0 = blockIdx.y * 32;
    __shared__ float tile[32][33];
    const int tx = threadIdx.x, ty = threadIdx.y;
    const float* V = v + (size_t)h * Nn * D;
    for (int r = ty; r < 32; r += 8)
        tile[r][tx] = V[(size_t)(k0 + r) * D + d0 + tx];
    __syncthreads();
    for (int r = ty; r < 32; r += 8) {
        float val = tile[tx][r];
        __nv_bfloat16 hb = __float2bfloat16_rn(val);
        float rem = val - __bfloat162float(hb);
        __nv_bfloat16 lb = __float2bfloat16_rn(rem);
        size_t o = (size_t)h * D * Nn + (size_t)(d0 + r) * Nn + k0 + tx;
        g_vth[o] = hb;
        g_vtl[o] = lb;
    }
}

// =============================================================================
// K1: S = scale * Q K^T via mma.sync bf16, 3-way split (6 products)
//     256 threads, 8 warps, warp tile 64(m) x 32(n); A planes register-cached
// =============================================================================
__global__ __launch_bounds__(256) void qk_mma_kernel() {
    extern __shared__ char smem[];
    const uint32_t sb = smem_to_u32(smem);
    const int t = threadIdx.x, lane = t & 31, wid = t >> 5;
    const int h = blockIdx.z, bm = blockIdx.x * 128, bn = blockIdx.y * 128;

    {   // fill 6 planes
        const size_t qg = (size_t)h * Nn * D + (size_t)bm * D;
        const size_t kg = (size_t)h * Nn * D + (size_t)bn * D;
        const __nv_bfloat16* s0 = g_qa + qg;
        const __nv_bfloat16* s1 = g_qb + qg;
        const __nv_bfloat16* s2 = g_qc + qg;
        const __nv_bfloat16* s3 = g_ka + kg;
        const __nv_bfloat16* s4 = g_kb + kg;
        const __nv_bfloat16* s5 = g_kc + kg;
        for (int i = t; i < 2048; i += 256) {
            int row = i >> 4, c16 = i & 15;
            uint32_t o = sw_off(row, c16);
            size_t g = (size_t)row * D + c16 * 8;
            *reinterpret_cast<uint4*>(smem + o)             = *reinterpret_cast<const uint4*>(s0 + g);
            *reinterpret_cast<uint4*>(smem + PLANE + o)     = *reinterpret_cast<const uint4*>(s1 + g);
            *reinterpret_cast<uint4*>(smem + 2 * PLANE + o) = *reinterpret_cast<const uint4*>(s2 + g);
            *reinterpret_cast<uint4*>(smem + 3 * PLANE + o) = *reinterpret_cast<const uint4*>(s3 + g);
            *reinterpret_cast<uint4*>(smem + 4 * PLANE + o) = *reinterpret_cast<const uint4*>(s4 + g);
            *reinterpret_cast<uint4*>(smem + 5 * PLANE + o) = *reinterpret_cast<const uint4*>(s5 + g);
        }
    }
    __syncthreads();

    const int m0 = (wid >> 2) * 64, n0 = (wid & 3) * 32;
    float acc[4][4][4];
#pragma unroll
    for (int i = 0; i < 4; i++)
#pragma unroll
        for (int j = 0; j < 4; j++)
#pragma unroll
            for (int c = 0; c < 4; c++) acc[i][j][c] = 0.f;

#pragma unroll
    for (int kk = 0; kk < 8; kk++) {
        const int arow = (lane & 15), ach = kk * 2 + (lane >> 4);
        uint32_t A[3][4][4];
#pragma unroll
        for (int ai = 0; ai < 3; ai++)
#pragma unroll
            for (int mi = 0; mi < 4; mi++)
                ldsm_x4(A[ai][mi][0], A[ai][mi][1], A[ai][mi][2], A[ai][mi][3],
                        sb + ai * PLANE + sw_off(m0 + mi * 16 + arow, ach));
#pragma unroll
        for (int bi = 0; bi < 3; bi++) {
            uint32_t B[4][2];
#pragma unroll
            for (int nj = 0; nj < 2; nj++) {
                int row = n0 + nj * 16 + arow;
                uint32_t r0, r1, r2, r3;
                ldsm_x4(r0, r1, r2, r3, sb + (3 + bi) * PLANE + sw_off(row, ach));
                B[nj * 2][0] = r0; B[nj * 2][1] = r2;
                B[nj * 2 + 1][0] = r1; B[nj * 2 + 1][1] = r3;
            }
            const int nA = 3 - bi;   // Ka:{Qa,Qb,Qc} Kb:{Qa,Qb} Kc:{Qa}
#pragma unroll
            for (int ai = 0; ai < 3; ai++) {
                if (ai >= nA) continue;
#pragma unroll
                for (int mi = 0; mi < 4; mi++)
#pragma unroll
                    for (int n8 = 0; n8 < 4; n8++)
                        mma_bf16(acc[mi][n8], A[ai][mi], B[n8]);
            }
        }
    }

    const float scale = 0.08838834764831845f;
    float* S = g_S + (size_t)h * Nn * Nn;
#pragma unroll
    for (int mi = 0; mi < 4; mi++) {
#pragma unroll
        for (int n8 = 0; n8 < 4; n8++) {
            int r = bm + m0 + mi * 16 + (lane >> 2);
            int c = bn + n0 + n8 * 8 + (lane & 3) * 2;
            float2 v01 = make_float2(acc[mi][n8][0] * scale, acc[mi][n8][1] * scale);
            float2 v23 = make_float2(acc[mi][n8][2] * scale, acc[mi][n8][3] * scale);
            *reinterpret_cast<float2*>(&S[(size_t)r * Nn + c]) = v01;
            *reinterpret_cast<float2*>(&S[(size_t)(r + 8) * Nn + c]) = v23;
        }
    }
}

// =============================================================================
// K2: fused row softmax + group column sums; P written as bf16 hi/lo planes
//     grid (2G, H): each CTA does 96 rows of one group; partial cs via atomics
// =============================================================================
__global__ __launch_bounds__(256) void softmax_cs_kernel() {
    const int g = blockIdx.x >> 1, half = blockIdx.x & 1, h = blockIdx.y;
    const int t = threadIdx.x, lane = t & 31, warp = t >> 5;

    __shared__ float colsum[Nn];
    __shared__ float redm[8];
    __shared__ float reds[8];

    for (int j = t; j < Nn; j += 256) colsum[j] = 0.f;
    __syncthreads();

    const int r0 = half * 96;
    for (int r = r0; r < r0 + 96; r++) {
        const int row = g * BMQ + r;
        const float4* S4 = reinterpret_cast<const float4*>(
            g_S + (size_t)h * Nn * Nn + (size_t)row * Nn);

        float4 v0 = S4[t], v1 = S4[t + 256], v2 = S4[t + 512];
        float mx = fmaxf(fmaxf(fmaxf(v0.x, v0.y), fmaxf(v0.z, v0.w)),
                   fmaxf(fmaxf(fmaxf(v1.x, v1.y), fmaxf(v1.z, v1.w)),
                         fmaxf(fmaxf(v2.x, v2.y), fmaxf(v2.z, v2.w))));
#pragma unroll
        for (int o = 16; o > 0; o >>= 1) mx = fmaxf(mx, __shfl_xor_sync(0xffffffffu, mx, o));
        if (lane == 0) redm[warp] = mx;
        __syncthreads();
        float rowmax = redm[0];
#pragma unroll
        for (int w = 1; w < 8; w++) rowmax = fmaxf(rowmax, redm[w]);

        v0.x = expf(v0.x - rowmax); v0.y = expf(v0.y - rowmax);
        v0.z = expf(v0.z - rowmax); v0.w = expf(v0.w - rowmax);
        v1.x = expf(v1.x - rowmax); v1.y = expf(v1.y - rowmax);
        v1.z = expf(v1.z - rowmax); v1.w = expf(v1.w - rowmax);
        v2.x = expf(v2.x - rowmax); v2.y = expf(v2.y - rowmax);
        v2.z = expf(v2.z - rowmax); v2.w = expf(v2.w - rowmax);
        float sum = (v0.x + v0.y + v0.z + v0.w) + (v1.x + v1.y + v1.z + v1.w)
                  + (v2.x + v2.y + v2.z + v2.w);
#pragma unroll
        for (int o = 16; o > 0; o >>= 1) sum += __shfl_xor_sync(0xffffffffu, sum, o);
        if (lane == 0) reds[warp] = sum;
        __syncthreads();
        float tot = reds[0];
#pragma unroll
        for (int w = 1; w < 8; w++) tot += reds[w];
        const float inv = 1.f / tot;

        __nv_bfloat16* phr = g_ph + (size_t)h * Nn * Nn + (size_t)row * Nn;
        __nv_bfloat16* plr = g_pl + (size_t)h * Nn * Nn + (size_t)row * Nn;
        float4 vv[3] = {v0, v1, v2};
        int jj[3] = {t * 4, (t + 256) * 4, (t + 512) * 4};
#pragma unroll
        for (int s = 0; s < 3; s++) {
            float p0 = vv[s].x * inv, p1 = vv[s].y * inv,
                  p2 = vv[s].z * inv, p3 = vv[s].w * inv;
            int j = jj[s];
            colsum[j] += p0; colsum[j + 1] += p1; colsum[j + 2] += p2; colsum[j + 3] += p3;
            unsigned short h0 = __bfloat16_as_ushort(__float2bfloat16_rn(p0));
            unsigned short h1 = __bfloat16_as_ushort(__float2bfloat16_rn(p1));
            unsigned short h2 = __bfloat16_as_ushort(__float2bfloat16_rn(p2));
            unsigned short h3 = __bfloat16_as_ushort(__float2bfloat16_rn(p3));
            unsigned short l0 = __bfloat16_as_ushort(__float2bfloat16_rn(
                p0 - __bfloat162float(__ushort_as_bfloat16(h0))));
            unsigned short l1 = __bfloat16_as_ushort(__float2bfloat16_rn(
                p1 - __bfloat162float(__ushort_as_bfloat16(h1))));
            unsigned short l2 = __bfloat16_as_ushort(__float2bfloat16_rn(
                p2 - __bfloat162float(__ushort_as_bfloat16(h2))));
            unsigned short l3 = __bfloat16_as_ushort(__float2bfloat16_rn(
                p3 - __bfloat162float(__ushort_as_bfloat16(h3))));
            uint2 hw, lw;
            hw.x = (uint32_t)h0 | ((uint32_t)h1 << 16);
            hw.y = (uint32_t)h2 | ((uint32_t)h3 << 16);
            lw.x = (uint32_t)l0 | ((uint32_t)l1 << 16);
            lw.y = (uint32_t)l2 | ((uint32_t)l3 << 16);
            *reinterpret_cast<uint2*>(phr + j) = hw;
            *reinterpret_cast<uint2*>(plr + j) = lw;
        }
        __syncthreads();   // protect redm/reds for next row
    }

    float* cs = g_cs + (h * G + g) * Nn;
    for (int j = t; j < Nn; j += 256) atomicAdd(&cs[j], colsum[j]);
}

// =============================================================================
// K3: top-896 radix select + threefry random mask -> bitmask
// =============================================================================
__global__ __launch_bounds__(256) void select_kernel() {
    const int hg = blockIdx.x;
    const float* cs = g_cs + hg * Nn;
    const int t = threadIdx.x;

    __shared__ unsigned keys[Nn];
    __shared__ unsigned hist[256];
    __shared__ unsigned char mk[Nn];
    __shared__ unsigned sh_prefix, sh_need;

    for (int j = t; j < Nn; j += 256) {
        unsigned u = __float_as_uint(cs[j]);
        keys[j] = (u & 0x80000000u) ? ~u : (u | 0x80000000u);
        mk[j] = 0;
    }
    __syncthreads();

    unsigned prefix = 0, kneed = TOPK;
    for (int shift = 24; shift >= 0; shift -= 8) {
        hist[t] = 0;
        __syncthreads();
        const unsigned himask = (shift == 24) ? 0u : (0xFFFFFFFFu << (shift + 8));
        for (int j = t; j < Nn; j += 256) {
            unsigned u = keys[j];
            if (((u ^ prefix) & himask) == 0)
                atomicAdd(&hist[(u >> shift) & 255u], 1u);
        }
        __syncthreads();
        if (t == 0) {
            unsigned cum = 0; int b = 255;
            for (; b > 0; b--) {
                if (cum + hist[b] >= kneed) break;
                cum += hist[b];
            }
            sh_prefix = prefix | ((unsigned)b << shift);
            sh_need   = kneed - cum;
        }
        __syncthreads();
        prefix = sh_prefix; kneed = sh_need;
        __syncthreads();
    }
    const unsigned T = prefix;

    for (int j = t; j < Nn; j += 256)
        if (keys[j] > T) mk[j] = 1;
    __syncthreads();
    if (t == 0) {
        int need = (int)kneed;
        for (int j = 0; j < Nn && need > 0; j++)
            if (keys[j] == T) { mk[j] = 1; need--; }
    }
    __syncthreads();

    uint2 hk = tf2x32(0u, 1u, 0u, 0u);
    uint2 lk = tf2x32(0u, 1u, 0u, 1u);
    for (int j = t; j < Nn; j += 256) {
        unsigned f = (unsigned)(hg * Nn + j);
        unsigned hi = tf_bits32(hk.x, hk.y, f);
        unsigned lo = tf_bits32(lk.x, lk.y, f);
        unsigned off = ((hi % 100u) * 96u + (lo % 100u)) % 100u;
        if (off == 0u) mk[j] = 1;
    }
    __syncthreads();

    if (t < 96) {
        unsigned w = 0;
#pragma unroll
        for (int b = 0; b < 32; b++)
            if (mk[t * 32 + b]) w |= (1u << b);
        g_mask[hg * 96 + t] = w;
    }
}

// =============================================================================
// K4: fused PV — dense O, masked SP, out2 = O - SP/den; P planes pre-split
//     256 threads, 8 warps, warp tile 64(m) x 32(d)
// =============================================================================
__global__ __launch_bounds__(256) void pv_fused_kernel(float* __restrict__ out) {
    extern __shared__ char smem[];
    const uint32_t sb = smem_to_u32(smem);
    uint32_t* mskS = reinterpret_cast<uint32_t*>(smem + 6 * PLANE);   // [2][96]
    float*   den  = reinterpret_cast<float*>(smem + 6 * PLANE + 768); // [128]
    const int t = threadIdx.x, lane = t & 31, wid = t >> 5;
    const int h = blockIdx.z, bm = blockIdx.x * 128;

    const int ga = bm / BMQ;
    const int gb = (bm + 127) / BMQ;
    if (t < 128) den[t] = 0.f;
    if (t >= 128 && t < 224) mskS[t - 128] = g_mask[(h * G + ga) * 96 + (t - 128)];
    if (t >= 224 && t < 256) {
        for (int w = t - 224; w < 96; w += 32)
            mskS[96 + w] = g_mask[(h * G + gb) * 96 + w];
    }
    __syncthreads();

    const __nv_bfloat16* ph = g_ph + (size_t)h * Nn * Nn + (size_t)bm * Nn;
    const __nv_bfloat16* pl = g_pl + (size_t)h * Nn * Nn + (size_t)bm * Nn;
    const __nv_bfloat16* vh = g_vth + (size_t)h * D * Nn;
    const __nv_bfloat16* vl = g_vtl + (size_t)h * D * Nn;

    const int m0 = (wid >> 2) * 64, n0 = (wid & 3) * 32;
    float accD[4][4][4], accM[4][4][4];
#pragma unroll
    for (int i = 0; i < 4; i++)
#pragma unroll
        for (int j = 0; j < 4; j++)
#pragma unroll
            for (int c = 0; c < 4; c++) { accD[i][j][c] = 0.f; accM[i][j][c] = 0.f; }

    for (int kc = 0; kc < 24; kc++) {
        if (kc) __syncthreads();
        for (int i = t; i < 2048; i += 256) {
            int row = i >> 4, c16 = i & 15;
            uint32_t o = sw_off(row, c16);
            const int colbase = kc * 128 + c16 * 8;
            const int gsel = ((bm + row) >= (ga + 1) * BMQ) ? 1 : 0;
            const uint32_t mbits = mskS[gsel * 96 + (colbase >> 5)] >> (colbase & 31);

            size_t goff = (size_t)row * Nn + colbase;
            uint4 hq = *reinterpret_cast<const uint4*>(ph + goff);
            uint4 lq = *reinterpret_cast<const uint4*>(pl + goff);
            *reinterpret_cast<uint4*>(smem + o) = hq;
            *reinterpret_cast<uint4*>(smem + PLANE + o) = lq;

            // masked planes: AND with per-halfword select (bf16 0x0000 == +0)
            uint32_t s0 = ((mbits & 1u) ? 0xFFFFu : 0u) | ((mbits & 2u) ? 0xFFFF0000u : 0u);
            uint32_t s1 = ((mbits & 4u) ? 0xFFFFu : 0u) | ((mbits & 8u) ? 0xFFFF0000u : 0u);
            uint32_t s2 = ((mbits & 16u) ? 0xFFFFu : 0u) | ((mbits & 32u) ? 0xFFFF0000u : 0u);
            uint32_t s3 = ((mbits & 64u) ? 0xFFFFu : 0u) | ((mbits & 128u) ? 0xFFFF0000u : 0u);
            uint4 mh = make_uint4(hq.x & s0, hq.y & s1, hq.z & s2, hq.w & s3);
            uint4 ml = make_uint4(lq.x & s0, lq.y & s1, lq.z & s2, lq.w & s3);
            *reinterpret_cast<uint4*>(smem + 2 * PLANE + o) = mh;
            *reinterpret_cast<uint4*>(smem + 3 * PLANE + o) = ml;

            if (mbits & 0xFFu) {
                float2 a0 = __bfloat1622float2(*reinterpret_cast<__nv_bfloat162*>(&mh.x));
                float2 a1 = __bfloat1622float2(*reinterpret_cast<__nv_bfloat162*>(&mh.y));
                float2 a2 = __bfloat1622float2(*reinterpret_cast<__nv_bfloat162*>(&mh.z));
                float2 a3 = __bfloat1622float2(*reinterpret_cast<__nv_bfloat162*>(&mh.w));
                float2 b0 = __bfloat1622float2(*reinterpret_cast<__nv_bfloat162*>(&ml.x));
                float2 b1 = __bfloat1622float2(*reinterpret_cast<__nv_bfloat162*>(&ml.y));
                float2 b2 = __bfloat1622float2(*reinterpret_cast<__nv_bfloat162*>(&ml.z));
                float2 b3 = __bfloat1622float2(*reinterpret_cast<__nv_bfloat162*>(&ml.w));
                float dsum = (a0.x + a0.y + a1.x + a1.y + a2.x + a2.y + a3.x + a3.y)
                           + (b0.x + b0.y + b1.x + b1.y + b2.x + b2.y + b3.x + b3.y);
                atomicAdd(&den[row], dsum);
            }

            *reinterpret_cast<uint4*>(smem + 4 * PLANE + o) = *reinterpret_cast<const uint4*>(vh + goff);
            *reinterpret_cast<uint4*>(smem + 5 * PLANE + o) = *reinterpret_cast<const uint4*>(vl + goff);
        }
        __syncthreads();

#pragma unroll
        for (int kk = 0; kk < 8; kk++) {
            const int arow = (lane & 15), ach = kk * 2 + (lane >> 4);
            uint32_t Bh[4][2], Bl[4][2];
#pragma unroll
            for (int nj = 0; nj < 2; nj++) {
                int row = n0 + nj * 16 + arow;
                uint32_t r0, r1, r2, r3;
                ldsm_x4(r0, r1, r2, r3, sb + 4 * PLANE + sw_off(row, ach));
                Bh[nj * 2][0] = r0; Bh[nj * 2][1] = r2;
                Bh[nj * 2 + 1][0] = r1; Bh[nj * 2 + 1][1] = r3;
                ldsm_x4(r0, r1, r2, r3, sb + 5 * PLANE + sw_off(row, ach));
                Bl[nj * 2][0] = r0; Bl[nj * 2][1] = r2;
                Bl[nj * 2 + 1][0] = r1; Bl[nj * 2 + 1][1] = r3;
            }
#pragma unroll
            for (int mi = 0; mi < 4; mi++) {
                int row = m0 + mi * 16 + arow;
                uint32_t Ah[4], Al[4], Amh[4], Aml[4];
                ldsm_x4(Ah[0], Ah[1], Ah[2], Ah[3], sb + sw_off(row, ach));
                ldsm_x4(Al[0], Al[1], Al[2], Al[3], sb + PLANE + sw_off(row, ach));
                ldsm_x4(Amh[0], Amh[1], Amh[2], Amh[3], sb + 2 * PLANE + sw_off(row, ach));
                ldsm_x4(Aml[0], Aml[1], Aml[2], Aml[3], sb + 3 * PLANE + sw_off(row, ach));
#pragma unroll
                for (int n8 = 0; n8 < 4; n8++) {
                    mma_bf16(accD[mi][n8], Ah, Bh[n8]);
                    mma_bf16(accD[mi][n8], Al, Bh[n8]);
                    mma_bf16(accD[mi][n8], Ah, Bl[n8]);
                    mma_bf16(accM[mi][n8], Amh, Bh[n8]);
                    mma_bf16(accM[mi][n8], Aml, Bh[n8]);
                    mma_bf16(accM[mi][n8], Amh, Bl[n8]);
                }
            }
        }
    }
    __syncthreads();

    float* O  = out + (size_t)h * Nn * D;
    float* O2 = out + (size_t)H * Nn * D + (size_t)h * Nn * D;
#pragma unroll
    for (int mi = 0; mi < 4; mi++) {
#pragma unroll
        for (int n8 = 0; n8 < 4; n8++) {
            int rl0 = m0 + mi * 16 + (lane >> 2);
            int rl1 = rl0 + 8;
            int c = n0 + n8 * 8 + (lane & 3) * 2;
            float inv0 = 1.f / den[rl0];
            float inv1 = 1.f / den[rl1];
            float2 d01 = make_float2(accD[mi][n8][0], accD[mi][n8][1]);
            float2 d23 = make_float2(accD[mi][n8][2], accD[mi][n8][3]);
            *reinterpret_cast<float2*>(&O[(size_t)(bm + rl0) * D + c]) = d01;
            *reinterpret_cast<float2*>(&O[(size_t)(bm + rl1) * D + c]) = d23;
            float2 s01 = make_float2(d01.x - accM[mi][n8][0] * inv0,
                                     d01.y - accM[mi][n8][1] * inv0);
            float2 s23 = make_float2(d23.x - accM[mi][n8][2] * inv1,
                                     d23.y - accM[mi][n8][3] * inv1);
            *reinterpret_cast<float2*>(&O2[(size_t)(bm + rl0) * D + c]) = s01;
            *reinterpret_cast<float2*>(&O2[(size_t)(bm + rl1) * D + c]) = s23;
        }
    }
}

// =============================================================================
extern "C" void kernel_launch(void* const* d_in, const int* in_sizes, int n_in,
                              void* d_out, int out_size) {
    const float* q = (const float*)d_in[0];
    const float* k = (const float*)d_in[1];
    const float* v = (const float*)d_in[2];
    float* out = (float*)d_out;

    const int SMEM_QK = 6 * PLANE;             // 192 KB
    const int SMEM_PV = 6 * PLANE + 768 + 512; // 192 KB + masks + den
    cudaFuncSetAttribute(qk_mma_kernel, cudaFuncAttributeMaxDynamicSharedMemorySize, SMEM_QK);
    cudaFuncSetAttribute(pv_fused_kernel, cudaFuncAttributeMaxDynamicSharedMemorySize, SMEM_PV);

    split_qk_kernel<<<dim3(9216, 2), 256>>>(q, k);
    vtrans_kernel<<<dim3(Nn / 32, D / 32, H), dim3(32, 8)>>>(v);
    qk_mma_kernel<<<dim3(24, 24, H), 256, SMEM_QK>>>();
    softmax_cs_kernel<<<dim3(2 * G, H), 256>>>();
    select_kernel<<<HG, 256>>>();
    pv_fused_kernel<<<dim3(24, 1, H), 256, SMEM_PV>>>(out);
}